// round 2
// baseline (speedup 1.0000x reference)
#include <cuda_runtime.h>
#include <math.h>

// ---------------------------------------------------------------------------
// FieldPredictionNetwork:  B=32768, G=512, H0=1024, H1=512, W=64, MODES=32, FD=128
// Batch-axis FFT: 32768 = 128 (N1) x 256 (N2), two-step Cooley-Tukey (Stockham).
// ---------------------------------------------------------------------------

#define NB 32768

// -------------------- scratch (device globals: no allocation allowed) ------
__device__ float  g_h0[NB * 1024];         // after GEMM1+relu
__device__ float  g_h1[NB * 512];          // after GEMM2+relu
__device__ float  g_xr[NB * 64];           // after GEMM3+relu (real)
__device__ float2 g_bufA[NB * 64];         // complex ping
__device__ float2 g_bufB[NB * 64];         // complex pong
__device__ float2 g_Z[NB * 64];            // 2-step FFT intermediate
__device__ float2 g_dftF[64 * 64];         // e^{-2pi i a b / 64}
__device__ float2 g_dftI[64 * 64];         // e^{+2pi i a b / 64} / 64
__device__ float2 g_P[64];                 // sum_{m: w0>=0} w1*w0*phase
__device__ float2 g_M[64];                 // sum_{m: w0<0 } w1*|w0|*phase

// -------------------- table init (runs every launch; deterministic) --------
__global__ void init_tables(const float* __restrict__ w0,
                            const float* __restrict__ w1)
{
    const double TWO_PI = 6.283185307179586476925286766559;
    int tid = threadIdx.x;
    for (int i = tid; i < 4096; i += blockDim.x) {
        int a = i >> 6, b = i & 63;
        int t = (a * b) & 63;
        double ang = -TWO_PI * (double)t / 64.0;   // forward sign
        double s, c;
        sincos(ang, &s, &c);
        g_dftF[i] = make_float2((float)c, (float)s);                    // e^{-i th}
        g_dftI[i] = make_float2((float)(c / 64.0), (float)(-s / 64.0)); // e^{+i th}/64
    }
    if (tid < 64) {
        int w = tid;
        double pr = 0, pi = 0, mr = 0, mi = 0;
        for (int m = 0; m < 32; m++) {
            float a = w0[m * 64 + w];
            float b = w1[m * 64 + w];
            double ang = TWO_PI * (double)m / 32.0;
            double s, c;
            sincos(ang, &s, &c);
            double coef = (double)b * fabs((double)a);
            if (a >= 0.0f) { pr += coef * c; pi += coef * s; }
            else           { mr += coef * c; mi += coef * s; }
        }
        g_P[w] = make_float2((float)pr, (float)pi);
        g_M[w] = make_float2((float)mr, (float)mi);
    }
}

// -------------------- fp32 SGEMM (NT) + bias + relu -------------------------
// SEL=0: A=ext(geom), C=g_h0 | SEL=1: A=g_h0, C=g_h1 | SEL=2: A=g_h1, C=g_xr
template <int BN, int TN, int SEL>
__global__ __launch_bounds__(256)
void sgemm_bias_relu(const float* __restrict__ Aext, const float* __restrict__ Bw,
                     const float* __restrict__ bias,
                     int M, int N, int K)
{
    const float* A = (SEL == 0) ? Aext : (SEL == 1 ? g_h0 : g_h1);
    float*       C = (SEL == 0) ? g_h0 : (SEL == 1 ? g_h1 : g_xr);

    const int BM = 128, BK = 16, TM = 8;
    __shared__ __align__(16) float As[BK][BM];
    __shared__ __align__(16) float Bs[BK][BN];
    const int tid = threadIdx.x;
    const int NT = BN / TN;              // threads along n
    const int tx = tid % NT;
    const int ty = tid / NT;
    const float* Ab = A + (size_t)blockIdx.y * BM * K;
    const float* Bb = Bw + (size_t)blockIdx.x * BN * K;

    float acc[TM][TN];
#pragma unroll
    for (int i = 0; i < TM; i++)
#pragma unroll
        for (int j = 0; j < TN; j++) acc[i][j] = 0.f;

    for (int k0 = 0; k0 < K; k0 += BK) {
#pragma unroll
        for (int i = 0; i < (BM * BK) / (256 * 4); i++) {
            int li = tid + i * 256;
            int row = li >> 2;
            int kc = (li & 3) << 2;
            float4 v = *reinterpret_cast<const float4*>(Ab + (size_t)row * K + k0 + kc);
            As[kc + 0][row] = v.x; As[kc + 1][row] = v.y;
            As[kc + 2][row] = v.z; As[kc + 3][row] = v.w;
        }
#pragma unroll
        for (int i = 0; i < (BN * BK) / (256 * 4); i++) {
            int li = tid + i * 256;
            int row = li >> 2;
            int kc = (li & 3) << 2;
            float4 v = *reinterpret_cast<const float4*>(Bb + (size_t)row * K + k0 + kc);
            Bs[kc + 0][row] = v.x; Bs[kc + 1][row] = v.y;
            Bs[kc + 2][row] = v.z; Bs[kc + 3][row] = v.w;
        }
        __syncthreads();
#pragma unroll
        for (int kk = 0; kk < BK; kk++) {
            float a[TM], b[TN];
#pragma unroll
            for (int i = 0; i < TM; i += 4) {
                float4 v = *reinterpret_cast<const float4*>(&As[kk][ty * TM + i]);
                a[i] = v.x; a[i + 1] = v.y; a[i + 2] = v.z; a[i + 3] = v.w;
            }
#pragma unroll
            for (int j = 0; j < TN; j += 4) {
                float4 v = *reinterpret_cast<const float4*>(&Bs[kk][tx * TN + j]);
                b[j] = v.x; b[j + 1] = v.y; b[j + 2] = v.z; b[j + 3] = v.w;
            }
#pragma unroll
            for (int i = 0; i < TM; i++)
#pragma unroll
                for (int j = 0; j < TN; j++)
                    acc[i][j] = fmaf(a[i], b[j], acc[i][j]);
        }
        __syncthreads();
    }
    int cn0 = blockIdx.x * BN + tx * TN;
    int cm0 = blockIdx.y * BM + ty * TM;
    float bv[TN];
#pragma unroll
    for (int j = 0; j < TN; j++) bv[j] = bias[cn0 + j];
#pragma unroll
    for (int i = 0; i < TM; i++)
#pragma unroll
        for (int j = 0; j < TN; j++) {
            float v = acc[i][j] + bv[j];
            C[(size_t)(cm0 + i) * N + cn0 + j] = v > 0.f ? v : 0.f;
        }
}

// -------------------- per-row forward DFT-64 (real -> complex) --------------
__global__ __launch_bounds__(1024)
void fwd_row_dft()
{
    __shared__ float sx[16][64];
    int tid = threadIdx.x;
    int row0 = blockIdx.x << 4;
    for (int i = tid; i < 16 * 64; i += 1024)
        sx[i >> 6][i & 63] = g_xr[(size_t)(row0 + (i >> 6)) * 64 + (i & 63)];
    __syncthreads();
    int r = tid >> 6, k = tid & 63;
    float re = 0.f, im = 0.f;
#pragma unroll 16
    for (int w = 0; w < 64; w++) {
        float2 t = g_dftF[(w << 6) + k];
        float xv = sx[r][w];
        re = fmaf(xv, t.x, re);
        im = fmaf(xv, t.y, im);
    }
    g_bufA[(size_t)(row0 + r) * 64 + k] = make_float2(re, im);
}

// -------------------- batch-axis FFT, step 1 --------------------------------
// For each n1: FFT-256 over n2 (b = n1 + 128*n2), then twiddle
// e^{sign*2pi i * n1*k2 / 32768}.  Reads g_bufA, writes g_Z[k2][n1][c].
__global__ __launch_bounds__(256)
void fft_b_step1(float sign)
{
    __shared__ float2 s0[8][256];
    __shared__ float2 s1[8][256];
    int tid = threadIdx.x;
    int n1 = blockIdx.x;                  // 0..127
    int c0 = blockIdx.y << 3;             // channel group of 8
    for (int i = tid; i < 2048; i += 256) {
        int n2 = i >> 3, ch = i & 7;
        s0[ch][n2] = g_bufA[(size_t)(n1 + (n2 << 7)) * 64 + c0 + ch];
    }
    __syncthreads();
    float2 (*src)[256] = s0;
    float2 (*dst)[256] = s1;
#pragma unroll
    for (int p = 0; p < 8; p++) {
        int Ns = 1 << p;
        float angc = sign * 3.14159265358979323846f / (float)Ns;
        for (int u = tid; u < 1024; u += 256) {
            int ch = u >> 7, j = u & 127;
            int jm = j & (Ns - 1);
            float2 a = src[ch][j];
            float2 b = src[ch][j + 128];
            float s, c;
            __sincosf(angc * (float)jm, &s, &c);
            float2 bw = make_float2(b.x * c - b.y * s, b.x * s + b.y * c);
            int idxD = ((j - jm) << 1) + jm;
            dst[ch][idxD]      = make_float2(a.x + bw.x, a.y + bw.y);
            dst[ch][idxD + Ns] = make_float2(a.x - bw.x, a.y - bw.y);
        }
        __syncthreads();
        float2 (*tmp)[256] = src; src = dst; dst = tmp;
    }
    for (int i = tid; i < 2048; i += 256) {
        int k2 = i >> 3, ch = i & 7;
        int t = (n1 * k2) & 32767;
        if (t > 16384) t -= 32768;        // map angle into (-pi, pi]
        float s, c;
        __sincosf(sign * 6.2831853071795864769f * (float)t * (1.0f / 32768.0f), &s, &c);
        float2 v = src[ch][k2];
        g_Z[((size_t)k2 * 128 + n1) * 64 + c0 + ch] =
            make_float2(v.x * c - v.y * s, v.x * s + v.y * c);
    }
}

// -------------------- batch-axis FFT, step 2 --------------------------------
// For each k2: FFT-128 over n1; output X[k2 + 256*k1]. Reads g_Z, writes g_bufB.
__global__ __launch_bounds__(256)
void fft_b_step2(float sign, float scale)
{
    __shared__ float2 s0[8][128];
    __shared__ float2 s1[8][128];
    int tid = threadIdx.x;
    int k2 = blockIdx.x;                  // 0..255
    int c0 = blockIdx.y << 3;
    for (int i = tid; i < 1024; i += 256) {
        int n1 = i >> 3, ch = i & 7;
        s0[ch][n1] = g_Z[((size_t)k2 * 128 + n1) * 64 + c0 + ch];
    }
    __syncthreads();
    float2 (*src)[128] = s0;
    float2 (*dst)[128] = s1;
#pragma unroll
    for (int p = 0; p < 7; p++) {
        int Ns = 1 << p;
        float angc = sign * 3.14159265358979323846f / (float)Ns;
        for (int u = tid; u < 512; u += 256) {
            int ch = u >> 6, j = u & 63;
            int jm = j & (Ns - 1);
            float2 a = src[ch][j];
            float2 b = src[ch][j + 64];
            float s, c;
            __sincosf(angc * (float)jm, &s, &c);
            float2 bw = make_float2(b.x * c - b.y * s, b.x * s + b.y * c);
            int idxD = ((j - jm) << 1) + jm;
            dst[ch][idxD]      = make_float2(a.x + bw.x, a.y + bw.y);
            dst[ch][idxD + Ns] = make_float2(a.x - bw.x, a.y - bw.y);
        }
        __syncthreads();
        float2 (*tmp)[128] = src; src = dst; dst = tmp;
    }
    for (int i = tid; i < 1024; i += 256) {
        int k1 = i >> 3, ch = i & 7;
        float2 v = src[ch][k1];
        g_bufB[(size_t)(k2 + (k1 << 8)) * 64 + c0 + ch] =
            make_float2(v.x * scale, v.y * scale);
    }
}

// -------------------- FNO core: P/M collapse + lin1 + crelu + lin2 ----------
// reads g_bufB (= fftn(x)); writes g_bufA.
__global__ __launch_bounds__(512)
void mid_kernel(const float* __restrict__ lin1W, const float* __restrict__ lin1b,
                const float* __restrict__ lin2W, const float* __restrict__ lin2b)
{
    __shared__ float L1t[64 * 64];   // [w][o]
    __shared__ float L2t[64 * 64];   // [w][o]
    __shared__ float yre[8][64], yim[8][64];
    __shared__ float tre[8][64], tim[8][64];
    __shared__ float2 sP[64], sM[64];
    int tid = threadIdx.x;
    int row0 = blockIdx.x << 3;
    for (int i = tid; i < 4096; i += 512) {
        int w = i >> 6, o = i & 63;
        L1t[i] = lin1W[(o << 6) + w];
        L2t[i] = lin2W[(o << 6) + w];
    }
    if (tid < 64) { sP[tid] = g_P[tid]; sM[tid] = g_M[tid]; }
    int r = tid >> 6, w = tid & 63;
    float2 xh = g_bufB[(size_t)(row0 + r) * 64 + w];
    __syncthreads();
    {
        float rp = fmaxf(xh.x, 0.f), rn = fmaxf(-xh.x, 0.f);
        float ip = fmaxf(xh.y, 0.f), im2 = fmaxf(-xh.y, 0.f);
        float2 P = sP[w], Mv = sM[w];
        yre[r][w] = rp * P.x - ip * P.y + rn * Mv.x - im2 * Mv.y;
        yim[r][w] = rp * P.y + ip * P.x + rn * Mv.y + im2 * Mv.x;
    }
    __syncthreads();
    int o = w;
    float re = lin1b[o], im = 0.f;
#pragma unroll 16
    for (int ww = 0; ww < 64; ww++) {
        float lw = L1t[(ww << 6) + o];
        re = fmaf(lw, yre[r][ww], re);
        im = fmaf(lw, yim[r][ww], im);
    }
    tre[r][o] = fmaxf(re, 0.f);
    tim[r][o] = fmaxf(im, 0.f);
    __syncthreads();
    re = lin2b[o]; im = 0.f;
#pragma unroll 16
    for (int ww = 0; ww < 64; ww++) {
        float lw = L2t[(ww << 6) + o];
        re = fmaf(lw, tre[r][ww], re);
        im = fmaf(lw, tim[r][ww], im);
    }
    g_bufA[(size_t)(row0 + r) * 64 + o] = make_float2(re, im);
}

// -------------------- per-row inverse DFT-64 + W_out + b_out ----------------
// reads g_bufB (inverse-b-FFT result), writes d_out [B,128] complex.
// interleaved=1: write (re,im) pairs (complex64 / float32-view layout);
// interleaved=0: write real part only (float32 out_size = B*FD case).
__global__ __launch_bounds__(1024)
void out_kernel(const float* __restrict__ Wout, const float* __restrict__ bout,
                float* __restrict__ outp, int interleaved)
{
    __shared__ float Wt[64 * 128];       // [w][f]
    __shared__ float2 sz[8][64];
    __shared__ float2 su[8][64];
    int tid = threadIdx.x;
    int row0 = blockIdx.x << 3;
    for (int i = tid; i < 8192; i += 1024) {
        int w = i >> 7, f = i & 127;
        Wt[i] = Wout[(f << 6) + w];
    }
    if (tid < 512) {
        int r = tid >> 6, k = tid & 63;
        sz[r][k] = g_bufB[(size_t)(row0 + r) * 64 + k];
    }
    __syncthreads();
    if (tid < 512) {
        int r = tid >> 6, w = tid & 63;
        float re = 0.f, im = 0.f;
#pragma unroll 16
        for (int k = 0; k < 64; k++) {
            float2 t = g_dftI[(k << 6) + w];
            float2 z = sz[r][k];
            re += z.x * t.x - z.y * t.y;
            im += z.x * t.y + z.y * t.x;
        }
        su[r][w] = make_float2(re, im);
    }
    __syncthreads();
    int r = tid >> 7, f = tid & 127;
    float re = bout[f], im = 0.f;
#pragma unroll 16
    for (int w = 0; w < 64; w++) {
        float lw = Wt[(w << 7) + f];
        float2 u = su[r][w];
        re = fmaf(lw, u.x, re);
        im = fmaf(lw, u.y, im);
    }
    size_t idx = (size_t)(row0 + r) * 128 + f;
    if (interleaved) {
        reinterpret_cast<float2*>(outp)[idx] = make_float2(re, im);
    } else {
        outp[idx] = re;
    }
}

// ---------------------------------------------------------------------------
extern "C" void kernel_launch(void* const* d_in, const int* in_sizes, int n_in,
                              void* d_out, int out_size)
{
    (void)in_sizes; (void)n_in;
    const float* geom  = (const float*)d_in[0];
    const float* W_in  = (const float*)d_in[1];
    const float* b_in  = (const float*)d_in[2];
    const float* W_h1  = (const float*)d_in[3];
    const float* b_h1  = (const float*)d_in[4];
    const float* W_h2  = (const float*)d_in[5];
    const float* b_h2  = (const float*)d_in[6];
    const float* w0    = (const float*)d_in[7];
    const float* w1    = (const float*)d_in[8];
    const float* lin1W = (const float*)d_in[9];
    const float* lin1b = (const float*)d_in[10];
    const float* lin2W = (const float*)d_in[11];
    const float* lin2b = (const float*)d_in[12];
    const float* Wout  = (const float*)d_in[13];
    const float* bout  = (const float*)d_in[14];

    init_tables<<<1, 512>>>(w0, w1);

    // MLP encoder (device-global scratch selected at compile time via SEL)
    sgemm_bias_relu<128, 8, 0><<<dim3(1024 / 128, NB / 128), 256>>>(
        geom, W_in, b_in, NB, 1024, 512);
    sgemm_bias_relu<128, 8, 1><<<dim3(512 / 128, NB / 128), 256>>>(
        nullptr, W_h1, b_h1, NB, 512, 1024);
    sgemm_bias_relu<64, 4, 2><<<dim3(1, NB / 128), 256>>>(
        nullptr, W_h2, b_h2, NB, 64, 512);

    // forward fftn: row DFT-64 then batch-axis FFT (two-step)
    fwd_row_dft<<<NB / 16, 1024>>>();
    fft_b_step1<<<dim3(128, 8), 256>>>(-1.f);
    fft_b_step2<<<dim3(256, 8), 256>>>(-1.f, 1.0f);

    // FNO core (mode collapse via P/M, lin1+crelu, lin2)
    mid_kernel<<<NB / 8, 512>>>(lin1W, lin1b, lin2W, lin2b);

    // inverse batch-axis FFT (scale 1/32768 here; 1/64 folded into g_dftI)
    fft_b_step1<<<dim3(128, 8), 256>>>(1.f);
    fft_b_step2<<<dim3(256, 8), 256>>>(1.f, 1.0f / 32768.0f);

    // inverse row DFT-64 + output projection.
    // Output layout decided by out_size: >= 2*B*FD floats -> interleaved
    // complex (matches complex64 / float32-view); else real-only (no OOB).
    int interleaved = (out_size >= 2 * NB * 128) ? 1 : 0;
    out_kernel<<<NB / 8, 1024>>>(Wout, bout, (float*)d_out, interleaved);
}

// round 4
// speedup vs baseline: 1.0658x; 1.0658x over previous
#include <cuda_runtime.h>
#include <cuda_bf16.h>
#include <math.h>
#include <cstdint>

// ---------------------------------------------------------------------------
// FieldPredictionNetwork:  B=32768, G=512, H0=1024, H1=512, W=64, MODES=32, FD=128
// MLP GEMMs: warp-level mma.sync bf16 hi/lo split (3 products, fp32 accum).
// (tcgen05 unavailable: harness compiles for base compute_103 target.)
// Batch-axis FFT: 32768 = 128 x 256 two-step Cooley-Tukey (Stockham).
// ---------------------------------------------------------------------------

#define NB 32768

// -------------------- scratch (device globals) ------------------------------
__device__ __nv_bfloat16 g_geomhi[NB * 512],  g_geomlo[NB * 512];
__device__ __nv_bfloat16 g_Winhi[1024 * 512], g_Winlo[1024 * 512];
__device__ __nv_bfloat16 g_Wh1hi[512 * 1024], g_Wh1lo[512 * 1024];
__device__ __nv_bfloat16 g_Wh2hi[64 * 512],   g_Wh2lo[64 * 512];
__device__ __nv_bfloat16 g_h0hi[NB * 1024],   g_h0lo[NB * 1024];
__device__ __nv_bfloat16 g_h1hi[NB * 512],    g_h1lo[NB * 512];
__device__ float  g_xr[NB * 64];
__device__ float2 g_bufA[NB * 64];
__device__ float2 g_bufB[NB * 64];
__device__ float2 g_Z[NB * 64];
__device__ float2 g_dftF[64 * 64];
__device__ float2 g_dftI[64 * 64];
__device__ float2 g_P[64];
__device__ float2 g_M[64];

// -------------------- small PTX wrappers ------------------------------------
__device__ __forceinline__ uint32_t smem_u32(const void* p) {
    uint32_t a;
    asm("{ .reg .u64 t; cvta.to.shared.u64 t, %1; cvt.u32.u64 %0, t; }" : "=r"(a) : "l"(p));
    return a;
}
__device__ __forceinline__ void ldsm_x4(uint32_t* r, uint32_t a) {
    asm volatile("ldmatrix.sync.aligned.m8n8.x4.shared.b16 {%0,%1,%2,%3}, [%4];"
                 : "=r"(r[0]), "=r"(r[1]), "=r"(r[2]), "=r"(r[3]) : "r"(a));
}
__device__ __forceinline__ void mma16816(float* c, const uint32_t* a,
                                         uint32_t b0, uint32_t b1) {
    asm volatile("mma.sync.aligned.m16n8k16.row.col.f32.bf16.bf16.f32 "
                 "{%0,%1,%2,%3}, {%4,%5,%6,%7}, {%8,%9}, {%0,%1,%2,%3};"
                 : "+f"(c[0]), "+f"(c[1]), "+f"(c[2]), "+f"(c[3])
                 : "r"(a[0]), "r"(a[1]), "r"(a[2]), "r"(a[3]), "r"(b0), "r"(b1));
}

// 16B-chunk XOR swizzle: row r (bf16 row of 32 elems = 4 chunks), chunk cc.
#define SWOFF(r, cc) ((uint32_t)((r) * 64 + (((cc) ^ (((r) >> 1) & 3)) << 4)))

// -------------------- fp32 -> bf16 hi/lo split ------------------------------
template <int SEL>
__global__ void split_kernel(const float* __restrict__ src, int n4)
{
    __nv_bfloat16* hi = (SEL == 0) ? g_geomhi : (SEL == 1) ? g_Winhi : (SEL == 2) ? g_Wh1hi : g_Wh2hi;
    __nv_bfloat16* lo = (SEL == 0) ? g_geomlo : (SEL == 1) ? g_Winlo : (SEL == 2) ? g_Wh1lo : g_Wh2lo;
    int i = blockIdx.x * blockDim.x + threadIdx.x;
    if (i >= n4) return;
    float4 v = reinterpret_cast<const float4*>(src)[i];
    __nv_bfloat16 h0 = __float2bfloat16(v.x), h1 = __float2bfloat16(v.y);
    __nv_bfloat16 h2 = __float2bfloat16(v.z), h3 = __float2bfloat16(v.w);
    __nv_bfloat162 a, b;
    a.x = h0; a.y = h1; b.x = h2; b.y = h3;
    reinterpret_cast<__nv_bfloat162*>(hi)[2 * i]     = a;
    reinterpret_cast<__nv_bfloat162*>(hi)[2 * i + 1] = b;
    a.x = __float2bfloat16(v.x - __bfloat162float(h0));
    a.y = __float2bfloat16(v.y - __bfloat162float(h1));
    b.x = __float2bfloat16(v.z - __bfloat162float(h2));
    b.y = __float2bfloat16(v.w - __bfloat162float(h3));
    reinterpret_cast<__nv_bfloat162*>(lo)[2 * i]     = a;
    reinterpret_cast<__nv_bfloat162*>(lo)[2 * i + 1] = b;
}

// -------------------- mma.sync bf16-split GEMM + bias + relu ----------------
// C[M,N] = relu(A[M,K] @ B[N,K]^T + bias).  CTA tile 128x64, BK=32.
// 8 warps = 2(m) x 4(n); warp tile 64x16 (4 m16 x 2 n8 frags).
// SEL 0: A=geom, B=W_in -> h0 (bf16 hi/lo)
// SEL 1: A=h0,   B=W_h1 -> h1 (bf16 hi/lo)
// SEL 2: A=h1,   B=W_h2 -> g_xr (fp32)
template <int SEL>
__global__ void __launch_bounds__(256)
mma_gemm(const float* __restrict__ bias, int M, int N, int K)
{
    const __nv_bfloat16* Ahi = (SEL == 0) ? g_geomhi : (SEL == 1) ? g_h0hi : g_h1hi;
    const __nv_bfloat16* Alo = (SEL == 0) ? g_geomlo : (SEL == 1) ? g_h0lo : g_h1lo;
    const __nv_bfloat16* Bhi = (SEL == 0) ? g_Winhi  : (SEL == 1) ? g_Wh1hi : g_Wh2hi;
    const __nv_bfloat16* Blo = (SEL == 0) ? g_Winlo  : (SEL == 1) ? g_Wh1lo : g_Wh2lo;

    __shared__ __align__(16) __nv_bfloat16 sAh[128 * 32];
    __shared__ __align__(16) __nv_bfloat16 sAl[128 * 32];
    __shared__ __align__(16) __nv_bfloat16 sBh[64 * 32];
    __shared__ __align__(16) __nv_bfloat16 sBl[64 * 32];

    const int tid = threadIdx.x;
    const int warp = tid >> 5, lane = tid & 31;
    const int wm = warp >> 2;            // 0..1
    const int wn = warp & 3;             // 0..3
    const int m0 = blockIdx.y * 128, n0 = blockIdx.x * 64;

    const uint32_t aAh = smem_u32(sAh), aAl = smem_u32(sAl);
    const uint32_t aBh = smem_u32(sBh), aBl = smem_u32(sBl);

    float acc[4][2][4];
#pragma unroll
    for (int i = 0; i < 4; i++)
#pragma unroll
        for (int j = 0; j < 2; j++)
#pragma unroll
            for (int q = 0; q < 4; q++) acc[i][j][q] = 0.f;

    // ldmatrix per-lane addressing
    const int row_off = (lane & 7) | (((lane >> 3) & 1) << 3);   // 0..15
    const int cc_half = lane >> 4;                               // 0,1

    const int ldr = tid >> 2;            // 0..63
    const int ldc = tid & 3;             // chunk 0..3

    for (int k0 = 0; k0 < K; k0 += 32) {
        // ---- A tiles: 128 rows x 4 chunks (2 rows per thread), hi+lo ----
        {
            size_t g0 = (size_t)(m0 + ldr) * K + k0 + ldc * 8;
            size_t g1 = (size_t)(m0 + ldr + 64) * K + k0 + ldc * 8;
            uint32_t o0 = SWOFF(ldr, ldc), o1 = SWOFF(ldr + 64, ldc);
            *reinterpret_cast<uint4*>(reinterpret_cast<char*>(sAh) + o0) = *reinterpret_cast<const uint4*>(Ahi + g0);
            *reinterpret_cast<uint4*>(reinterpret_cast<char*>(sAh) + o1) = *reinterpret_cast<const uint4*>(Ahi + g1);
            *reinterpret_cast<uint4*>(reinterpret_cast<char*>(sAl) + o0) = *reinterpret_cast<const uint4*>(Alo + g0);
            *reinterpret_cast<uint4*>(reinterpret_cast<char*>(sAl) + o1) = *reinterpret_cast<const uint4*>(Alo + g1);
        }
        // ---- B tiles: 64 rows x 4 chunks (1 per thread), hi+lo ----
        {
            size_t g = (size_t)(n0 + ldr) * K + k0 + ldc * 8;
            uint32_t o = SWOFF(ldr, ldc);
            *reinterpret_cast<uint4*>(reinterpret_cast<char*>(sBh) + o) = *reinterpret_cast<const uint4*>(Bhi + g);
            *reinterpret_cast<uint4*>(reinterpret_cast<char*>(sBl) + o) = *reinterpret_cast<const uint4*>(Blo + g);
        }
        __syncthreads();

#pragma unroll
        for (int s = 0; s < 2; s++) {
            const int cc = 2 * s + cc_half;
            uint32_t Afh[4][4], Afl[4][4], Bfh[4], Bfl[4];
#pragma unroll
            for (int mi = 0; mi < 4; mi++) {
                int r = wm * 64 + mi * 16 + row_off;
                ldsm_x4(Afh[mi], aAh + SWOFF(r, cc));
                ldsm_x4(Afl[mi], aAl + SWOFF(r, cc));
            }
            {
                int r = wn * 16 + row_off;
                ldsm_x4(Bfh, aBh + SWOFF(r, cc));
                ldsm_x4(Bfl, aBl + SWOFF(r, cc));
            }
#pragma unroll
            for (int mi = 0; mi < 4; mi++) {
#pragma unroll
                for (int ni = 0; ni < 2; ni++) {
                    mma16816(acc[mi][ni], Afh[mi], Bfh[ni], Bfh[ni + 2]);
                    mma16816(acc[mi][ni], Afh[mi], Bfl[ni], Bfl[ni + 2]);
                    mma16816(acc[mi][ni], Afl[mi], Bfh[ni], Bfh[ni + 2]);
                }
            }
        }
        __syncthreads();
    }

    // ---- epilogue: bias + relu (+ hi/lo re-split for SEL 0/1) ----
    const int g = lane >> 2, tg = lane & 3;
#pragma unroll
    for (int mi = 0; mi < 4; mi++) {
#pragma unroll
        for (int ni = 0; ni < 2; ni++) {
            int col = n0 + wn * 16 + ni * 8 + 2 * tg;
            float b0 = bias[col], b1 = bias[col + 1];
#pragma unroll
            for (int h = 0; h < 2; h++) {
                int row = m0 + wm * 64 + mi * 16 + g + h * 8;
                float v0 = acc[mi][ni][2 * h + 0] + b0;
                float v1 = acc[mi][ni][2 * h + 1] + b1;
                v0 = v0 > 0.f ? v0 : 0.f;
                v1 = v1 > 0.f ? v1 : 0.f;
                size_t idx = (size_t)row * N + col;
                if (SEL == 2) {
                    *reinterpret_cast<float2*>(g_xr + idx) = make_float2(v0, v1);
                } else {
                    __nv_bfloat16* Chi = (SEL == 0) ? g_h0hi : g_h1hi;
                    __nv_bfloat16* Clo = (SEL == 0) ? g_h0lo : g_h1lo;
                    __nv_bfloat162 hh, ll;
                    hh.x = __float2bfloat16(v0);
                    hh.y = __float2bfloat16(v1);
                    ll.x = __float2bfloat16(v0 - __bfloat162float(hh.x));
                    ll.y = __float2bfloat16(v1 - __bfloat162float(hh.y));
                    *reinterpret_cast<__nv_bfloat162*>(Chi + idx) = hh;
                    *reinterpret_cast<__nv_bfloat162*>(Clo + idx) = ll;
                }
            }
        }
    }
}

// -------------------- table init -------------------------------------------
__global__ void init_tables(const float* __restrict__ w0,
                            const float* __restrict__ w1)
{
    const double TWO_PI = 6.283185307179586476925286766559;
    int tid = threadIdx.x;
    for (int i = tid; i < 4096; i += blockDim.x) {
        int a = i >> 6, b = i & 63;
        int t = (a * b) & 63;
        double ang = -TWO_PI * (double)t / 64.0;
        double s, c;
        sincos(ang, &s, &c);
        g_dftF[i] = make_float2((float)c, (float)s);
        g_dftI[i] = make_float2((float)(c / 64.0), (float)(-s / 64.0));
    }
    if (tid < 64) {
        int w = tid;
        double pr = 0, pi = 0, mr = 0, mi = 0;
        for (int m = 0; m < 32; m++) {
            float a = w0[m * 64 + w];
            float b = w1[m * 64 + w];
            double ang = TWO_PI * (double)m / 32.0;
            double s, c;
            sincos(ang, &s, &c);
            double coef = (double)b * fabs((double)a);
            if (a >= 0.0f) { pr += coef * c; pi += coef * s; }
            else           { mr += coef * c; mi += coef * s; }
        }
        g_P[w] = make_float2((float)pr, (float)pi);
        g_M[w] = make_float2((float)mr, (float)mi);
    }
}

// -------------------- per-row forward DFT-64 --------------------------------
__global__ __launch_bounds__(1024)
void fwd_row_dft()
{
    __shared__ float sx[16][64];
    int tid = threadIdx.x;
    int row0 = blockIdx.x << 4;
    for (int i = tid; i < 16 * 64; i += 1024)
        sx[i >> 6][i & 63] = g_xr[(size_t)(row0 + (i >> 6)) * 64 + (i & 63)];
    __syncthreads();
    int r = tid >> 6, k = tid & 63;
    float re = 0.f, im = 0.f;
#pragma unroll 16
    for (int w = 0; w < 64; w++) {
        float2 t = g_dftF[(w << 6) + k];
        float xv = sx[r][w];
        re = fmaf(xv, t.x, re);
        im = fmaf(xv, t.y, im);
    }
    g_bufA[(size_t)(row0 + r) * 64 + k] = make_float2(re, im);
}

// -------------------- batch-axis FFT, step 1 --------------------------------
__global__ __launch_bounds__(256)
void fft_b_step1(float sign)
{
    __shared__ float2 s0[8][256];
    __shared__ float2 s1[8][256];
    int tid = threadIdx.x;
    int n1 = blockIdx.x;
    int c0 = blockIdx.y << 3;
    for (int i = tid; i < 2048; i += 256) {
        int n2 = i >> 3, ch = i & 7;
        s0[ch][n2] = g_bufA[(size_t)(n1 + (n2 << 7)) * 64 + c0 + ch];
    }
    __syncthreads();
    float2 (*src)[256] = s0;
    float2 (*dst)[256] = s1;
#pragma unroll
    for (int p = 0; p < 8; p++) {
        int Ns = 1 << p;
        float angc = sign * 3.14159265358979323846f / (float)Ns;
        for (int u = tid; u < 1024; u += 256) {
            int ch = u >> 7, j = u & 127;
            int jm = j & (Ns - 1);
            float2 a = src[ch][j];
            float2 b = src[ch][j + 128];
            float s, c;
            __sincosf(angc * (float)jm, &s, &c);
            float2 bw = make_float2(b.x * c - b.y * s, b.x * s + b.y * c);
            int idxD = ((j - jm) << 1) + jm;
            dst[ch][idxD]      = make_float2(a.x + bw.x, a.y + bw.y);
            dst[ch][idxD + Ns] = make_float2(a.x - bw.x, a.y - bw.y);
        }
        __syncthreads();
        float2 (*tmp)[256] = src; src = dst; dst = tmp;
    }
    for (int i = tid; i < 2048; i += 256) {
        int k2 = i >> 3, ch = i & 7;
        int t = (n1 * k2) & 32767;
        if (t > 16384) t -= 32768;
        float s, c;
        __sincosf(sign * 6.2831853071795864769f * (float)t * (1.0f / 32768.0f), &s, &c);
        float2 v = src[ch][k2];
        g_Z[((size_t)k2 * 128 + n1) * 64 + c0 + ch] =
            make_float2(v.x * c - v.y * s, v.x * s + v.y * c);
    }
}

// -------------------- batch-axis FFT, step 2 --------------------------------
__global__ __launch_bounds__(256)
void fft_b_step2(float sign, float scale)
{
    __shared__ float2 s0[8][128];
    __shared__ float2 s1[8][128];
    int tid = threadIdx.x;
    int k2 = blockIdx.x;
    int c0 = blockIdx.y << 3;
    for (int i = tid; i < 1024; i += 256) {
        int n1 = i >> 3, ch = i & 7;
        s0[ch][n1] = g_Z[((size_t)k2 * 128 + n1) * 64 + c0 + ch];
    }
    __syncthreads();
    float2 (*src)[128] = s0;
    float2 (*dst)[128] = s1;
#pragma unroll
    for (int p = 0; p < 7; p++) {
        int Ns = 1 << p;
        float angc = sign * 3.14159265358979323846f / (float)Ns;
        for (int u = tid; u < 512; u += 256) {
            int ch = u >> 6, j = u & 63;
            int jm = j & (Ns - 1);
            float2 a = src[ch][j];
            float2 b = src[ch][j + 64];
            float s, c;
            __sincosf(angc * (float)jm, &s, &c);
            float2 bw = make_float2(b.x * c - b.y * s, b.x * s + b.y * c);
            int idxD = ((j - jm) << 1) + jm;
            dst[ch][idxD]      = make_float2(a.x + bw.x, a.y + bw.y);
            dst[ch][idxD + Ns] = make_float2(a.x - bw.x, a.y - bw.y);
        }
        __syncthreads();
        float2 (*tmp)[128] = src; src = dst; dst = tmp;
    }
    for (int i = tid; i < 1024; i += 256) {
        int k1 = i >> 3, ch = i & 7;
        float2 v = src[ch][k1];
        g_bufB[(size_t)(k2 + (k1 << 8)) * 64 + c0 + ch] =
            make_float2(v.x * scale, v.y * scale);
    }
}

// -------------------- FNO core ---------------------------------------------
__global__ __launch_bounds__(512)
void mid_kernel(const float* __restrict__ lin1W, const float* __restrict__ lin1b,
                const float* __restrict__ lin2W, const float* __restrict__ lin2b)
{
    __shared__ float L1t[64 * 64];
    __shared__ float L2t[64 * 64];
    __shared__ float yre[8][64], yim[8][64];
    __shared__ float tre[8][64], tim[8][64];
    __shared__ float2 sP[64], sM[64];
    int tid = threadIdx.x;
    int row0 = blockIdx.x << 3;
    for (int i = tid; i < 4096; i += 512) {
        int w = i >> 6, o = i & 63;
        L1t[i] = lin1W[(o << 6) + w];
        L2t[i] = lin2W[(o << 6) + w];
    }
    if (tid < 64) { sP[tid] = g_P[tid]; sM[tid] = g_M[tid]; }
    int r = tid >> 6, w = tid & 63;
    float2 xh = g_bufB[(size_t)(row0 + r) * 64 + w];
    __syncthreads();
    {
        float rp = fmaxf(xh.x, 0.f), rn = fmaxf(-xh.x, 0.f);
        float ip = fmaxf(xh.y, 0.f), im2 = fmaxf(-xh.y, 0.f);
        float2 P = sP[w], Mv = sM[w];
        yre[r][w] = rp * P.x - ip * P.y + rn * Mv.x - im2 * Mv.y;
        yim[r][w] = rp * P.y + ip * P.x + rn * Mv.y + im2 * Mv.x;
    }
    __syncthreads();
    int o = w;
    float re = lin1b[o], im = 0.f;
#pragma unroll 16
    for (int ww = 0; ww < 64; ww++) {
        float lw = L1t[(ww << 6) + o];
        re = fmaf(lw, yre[r][ww], re);
        im = fmaf(lw, yim[r][ww], im);
    }
    tre[r][o] = fmaxf(re, 0.f);
    tim[r][o] = fmaxf(im, 0.f);
    __syncthreads();
    re = lin2b[o]; im = 0.f;
#pragma unroll 16
    for (int ww = 0; ww < 64; ww++) {
        float lw = L2t[(ww << 6) + o];
        re = fmaf(lw, tre[r][ww], re);
        im = fmaf(lw, tim[r][ww], im);
    }
    g_bufA[(size_t)(row0 + r) * 64 + o] = make_float2(re, im);
}

// -------------------- inverse row DFT-64 + W_out ----------------------------
__global__ __launch_bounds__(1024)
void out_kernel(const float* __restrict__ Wout, const float* __restrict__ bout,
                float* __restrict__ outp, int interleaved)
{
    __shared__ float Wt[64 * 128];
    __shared__ float2 sz[8][64];
    __shared__ float2 su[8][64];
    int tid = threadIdx.x;
    int row0 = blockIdx.x << 3;
    for (int i = tid; i < 8192; i += 1024) {
        int w = i >> 7, f = i & 127;
        Wt[i] = Wout[(f << 6) + w];
    }
    if (tid < 512) {
        int r = tid >> 6, k = tid & 63;
        sz[r][k] = g_bufB[(size_t)(row0 + r) * 64 + k];
    }
    __syncthreads();
    if (tid < 512) {
        int r = tid >> 6, w = tid & 63;
        float re = 0.f, im = 0.f;
#pragma unroll 16
        for (int k = 0; k < 64; k++) {
            float2 t = g_dftI[(k << 6) + w];
            float2 z = sz[r][k];
            re += z.x * t.x - z.y * t.y;
            im += z.x * t.y + z.y * t.x;
        }
        su[r][w] = make_float2(re, im);
    }
    __syncthreads();
    int r = tid >> 7, f = tid & 127;
    float re = bout[f], im = 0.f;
#pragma unroll 16
    for (int w = 0; w < 64; w++) {
        float lw = Wt[(w << 7) + f];
        float2 u = su[r][w];
        re = fmaf(lw, u.x, re);
        im = fmaf(lw, u.y, im);
    }
    size_t idx = (size_t)(row0 + r) * 128 + f;
    if (interleaved) {
        reinterpret_cast<float2*>(outp)[idx] = make_float2(re, im);
    } else {
        outp[idx] = re;
    }
}

// ---------------------------------------------------------------------------
extern "C" void kernel_launch(void* const* d_in, const int* in_sizes, int n_in,
                              void* d_out, int out_size)
{
    (void)in_sizes; (void)n_in;
    const float* geom  = (const float*)d_in[0];
    const float* W_in  = (const float*)d_in[1];
    const float* b_in  = (const float*)d_in[2];
    const float* W_h1  = (const float*)d_in[3];
    const float* b_h1  = (const float*)d_in[4];
    const float* W_h2  = (const float*)d_in[5];
    const float* b_h2  = (const float*)d_in[6];
    const float* w0    = (const float*)d_in[7];
    const float* w1    = (const float*)d_in[8];
    const float* lin1W = (const float*)d_in[9];
    const float* lin1b = (const float*)d_in[10];
    const float* lin2W = (const float*)d_in[11];
    const float* lin2b = (const float*)d_in[12];
    const float* Wout  = (const float*)d_in[13];
    const float* bout  = (const float*)d_in[14];

    init_tables<<<1, 512>>>(w0, w1);

    // hi/lo bf16 splits of GEMM inputs
    split_kernel<0><<<(NB * 512 / 4) / 256, 256>>>(geom, NB * 512 / 4);
    split_kernel<1><<<(1024 * 512 / 4) / 256, 256>>>(W_in, 1024 * 512 / 4);
    split_kernel<2><<<(512 * 1024 / 4) / 256, 256>>>(W_h1, 512 * 1024 / 4);
    split_kernel<3><<<(64 * 512 / 4) / 256, 256>>>(W_h2, 64 * 512 / 4);

    // MLP encoder on mma.sync bf16 (hi/lo split, fp32 accumulate)
    mma_gemm<0><<<dim3(1024 / 64, NB / 128), 256>>>(b_in, NB, 1024, 512);
    mma_gemm<1><<<dim3(512 / 64, NB / 128), 256>>>(b_h1, NB, 512, 1024);
    mma_gemm<2><<<dim3(1, NB / 128), 256>>>(b_h2, NB, 64, 512);

    // forward fftn
    fwd_row_dft<<<NB / 16, 1024>>>();
    fft_b_step1<<<dim3(128, 8), 256>>>(-1.f);
    fft_b_step2<<<dim3(256, 8), 256>>>(-1.f, 1.0f);

    // FNO core
    mid_kernel<<<NB / 8, 512>>>(lin1W, lin1b, lin2W, lin2b);

    // inverse batch-axis FFT
    fft_b_step1<<<dim3(128, 8), 256>>>(1.f);
    fft_b_step2<<<dim3(256, 8), 256>>>(1.f, 1.0f / 32768.0f);

    // inverse row DFT-64 + output projection
    int interleaved = (out_size >= 2 * NB * 128) ? 1 : 0;
    out_kernel<<<NB / 8, 1024>>>(Wout, bout, (float*)d_out, interleaved);
}

// round 5
// speedup vs baseline: 1.8325x; 1.7194x over previous
#include <cuda_runtime.h>
#include <cuda_bf16.h>
#include <math.h>
#include <cstdint>

// ---------------------------------------------------------------------------
// FieldPredictionNetwork:  B=32768, G=512, H0=1024, H1=512, W=64, MODES=32, FD=128
// MLP GEMMs: mma.sync bf16 hi/lo split, cp.async double-buffered.
// FFT: all twiddles precomputed (no MUFU in hot loops).
// ---------------------------------------------------------------------------

#define NB 32768

// -------------------- scratch (device globals) ------------------------------
__device__ __nv_bfloat16 g_geomhi[NB * 512],  g_geomlo[NB * 512];
__device__ __nv_bfloat16 g_Winhi[1024 * 512], g_Winlo[1024 * 512];
__device__ __nv_bfloat16 g_Wh1hi[512 * 1024], g_Wh1lo[512 * 1024];
__device__ __nv_bfloat16 g_Wh2hi[64 * 512],   g_Wh2lo[64 * 512];
__device__ __nv_bfloat16 g_h0hi[NB * 1024],   g_h0lo[NB * 1024];
__device__ __nv_bfloat16 g_h1hi[NB * 512],    g_h1lo[NB * 512];
__device__ float  g_xr[NB * 64];
__device__ float2 g_bufA[NB * 64];
__device__ float2 g_bufB[NB * 64];
__device__ float2 g_Z[NB * 64];
__device__ float2 g_dftF[64 * 64];
__device__ float2 g_dftI[64 * 64];
__device__ float2 g_P[64];
__device__ float2 g_M[64];
__device__ float2 g_stw1[256];   // stage twiddles FFT-256: idx Ns-1+jm, e^{-i pi jm/Ns}
__device__ float2 g_stw2[128];   // stage twiddles FFT-128
__device__ float2 g_btw[32768];  // e^{-2 pi i t / 32768}

// -------------------- small PTX wrappers ------------------------------------
__device__ __forceinline__ uint32_t smem_u32(const void* p) {
    uint32_t a;
    asm("{ .reg .u64 t; cvta.to.shared.u64 t, %1; cvt.u32.u64 %0, t; }" : "=r"(a) : "l"(p));
    return a;
}
__device__ __forceinline__ void ldsm_x4(uint32_t* r, uint32_t a) {
    asm volatile("ldmatrix.sync.aligned.m8n8.x4.shared.b16 {%0,%1,%2,%3}, [%4];"
                 : "=r"(r[0]), "=r"(r[1]), "=r"(r[2]), "=r"(r[3]) : "r"(a));
}
__device__ __forceinline__ void mma16816(float* c, const uint32_t* a,
                                         uint32_t b0, uint32_t b1) {
    asm volatile("mma.sync.aligned.m16n8k16.row.col.f32.bf16.bf16.f32 "
                 "{%0,%1,%2,%3}, {%4,%5,%6,%7}, {%8,%9}, {%0,%1,%2,%3};"
                 : "+f"(c[0]), "+f"(c[1]), "+f"(c[2]), "+f"(c[3])
                 : "r"(a[0]), "r"(a[1]), "r"(a[2]), "r"(a[3]), "r"(b0), "r"(b1));
}
__device__ __forceinline__ void cp16(uint32_t dst, const void* src) {
    asm volatile("cp.async.cg.shared.global [%0], [%1], 16;" :: "r"(dst), "l"(src));
}
#define CP_COMMIT()  asm volatile("cp.async.commit_group;" ::: "memory")
#define CP_WAIT(n)   asm volatile("cp.async.wait_group %0;" :: "n"(n) : "memory")

// 16B-chunk XOR swizzle: row r (bf16 row of 32 elems = 4 chunks), chunk cc.
#define SWOFF(r, cc) ((uint32_t)((r) * 64 + (((cc) ^ (((r) >> 1) & 3)) << 4)))

// -------------------- fp32 -> bf16 hi/lo split ------------------------------
template <int SEL>
__global__ void split_kernel(const float* __restrict__ src, int n4)
{
    __nv_bfloat16* hi = (SEL == 0) ? g_geomhi : (SEL == 1) ? g_Winhi : (SEL == 2) ? g_Wh1hi : g_Wh2hi;
    __nv_bfloat16* lo = (SEL == 0) ? g_geomlo : (SEL == 1) ? g_Winlo : (SEL == 2) ? g_Wh1lo : g_Wh2lo;
    int i = blockIdx.x * blockDim.x + threadIdx.x;
    if (i >= n4) return;
    float4 v = reinterpret_cast<const float4*>(src)[i];
    __nv_bfloat16 h0 = __float2bfloat16(v.x), h1 = __float2bfloat16(v.y);
    __nv_bfloat16 h2 = __float2bfloat16(v.z), h3 = __float2bfloat16(v.w);
    __nv_bfloat162 a, b;
    a.x = h0; a.y = h1; b.x = h2; b.y = h3;
    reinterpret_cast<__nv_bfloat162*>(hi)[2 * i]     = a;
    reinterpret_cast<__nv_bfloat162*>(hi)[2 * i + 1] = b;
    a.x = __float2bfloat16(v.x - __bfloat162float(h0));
    a.y = __float2bfloat16(v.y - __bfloat162float(h1));
    b.x = __float2bfloat16(v.z - __bfloat162float(h2));
    b.y = __float2bfloat16(v.w - __bfloat162float(h3));
    reinterpret_cast<__nv_bfloat162*>(lo)[2 * i]     = a;
    reinterpret_cast<__nv_bfloat162*>(lo)[2 * i + 1] = b;
}

// -------------------- mma.sync bf16-split GEMM + bias + relu ----------------
// C[M,N] = relu(A[M,K] @ B[N,K]^T + bias).  CTA 128x64, BK=32, double-buffered
// cp.async.  8 warps = 2(m) x 4(n); warp tile 64x16.
template <int SEL>
__global__ void __launch_bounds__(256)
mma_gemm(const float* __restrict__ bias, int M, int N, int K)
{
    const __nv_bfloat16* Ahi = (SEL == 0) ? g_geomhi : (SEL == 1) ? g_h0hi : g_h1hi;
    const __nv_bfloat16* Alo = (SEL == 0) ? g_geomlo : (SEL == 1) ? g_h0lo : g_h1lo;
    const __nv_bfloat16* Bhi = (SEL == 0) ? g_Winhi  : (SEL == 1) ? g_Wh1hi : g_Wh2hi;
    const __nv_bfloat16* Blo = (SEL == 0) ? g_Winlo  : (SEL == 1) ? g_Wh1lo : g_Wh2lo;

    __shared__ __align__(16) __nv_bfloat16 sAh[2][128 * 32];
    __shared__ __align__(16) __nv_bfloat16 sAl[2][128 * 32];
    __shared__ __align__(16) __nv_bfloat16 sBh[2][64 * 32];
    __shared__ __align__(16) __nv_bfloat16 sBl[2][64 * 32];

    const int tid = threadIdx.x;
    const int warp = tid >> 5, lane = tid & 31;
    const int wm = warp >> 2, wn = warp & 3;
    const int m0 = blockIdx.y * 128, n0 = blockIdx.x * 64;

    const uint32_t aAh[2] = { smem_u32(sAh[0]), smem_u32(sAh[1]) };
    const uint32_t aAl[2] = { smem_u32(sAl[0]), smem_u32(sAl[1]) };
    const uint32_t aBh[2] = { smem_u32(sBh[0]), smem_u32(sBh[1]) };
    const uint32_t aBl[2] = { smem_u32(sBl[0]), smem_u32(sBl[1]) };

    float acc[4][2][4];
#pragma unroll
    for (int i = 0; i < 4; i++)
#pragma unroll
        for (int j = 0; j < 2; j++)
#pragma unroll
            for (int q = 0; q < 4; q++) acc[i][j][q] = 0.f;

    const int row_off = (lane & 7) | (((lane >> 3) & 1) << 3);
    const int cc_half = lane >> 4;
    const int ldr = tid >> 2, ldc = tid & 3;
    const uint32_t oA0 = SWOFF(ldr, ldc), oA1 = SWOFF(ldr + 64, ldc);
    const int nchunk = K >> 5;

    // stage loader (6 x cp16 per thread)
#define LOAD_STAGE(kc, bf) do {                                                 \
        int _k0 = (kc) << 5;                                                    \
        size_t _g0 = (size_t)(m0 + ldr) * K + _k0 + ldc * 8;                    \
        size_t _g1 = (size_t)(m0 + ldr + 64) * K + _k0 + ldc * 8;               \
        cp16(aAh[bf] + oA0, Ahi + _g0);                                         \
        cp16(aAh[bf] + oA1, Ahi + _g1);                                         \
        cp16(aAl[bf] + oA0, Alo + _g0);                                         \
        cp16(aAl[bf] + oA1, Alo + _g1);                                         \
        size_t _gb = (size_t)(n0 + ldr) * K + _k0 + ldc * 8;                    \
        cp16(aBh[bf] + oA0, Bhi + _gb);                                         \
        cp16(aBl[bf] + oA0, Blo + _gb);                                         \
    } while (0)

    LOAD_STAGE(0, 0);
    CP_COMMIT();

    for (int kc = 0; kc < nchunk; kc++) {
        if (kc + 1 < nchunk) {
            LOAD_STAGE(kc + 1, (kc + 1) & 1);
            CP_COMMIT();
            CP_WAIT(1);
        } else {
            CP_WAIT(0);
        }
        __syncthreads();
        const int bf = kc & 1;
#pragma unroll
        for (int s = 0; s < 2; s++) {
            const int cc = 2 * s + cc_half;
            uint32_t Afh[4][4], Afl[4][4], Bfh[4], Bfl[4];
#pragma unroll
            for (int mi = 0; mi < 4; mi++) {
                int r = wm * 64 + mi * 16 + row_off;
                ldsm_x4(Afh[mi], aAh[bf] + SWOFF(r, cc));
                ldsm_x4(Afl[mi], aAl[bf] + SWOFF(r, cc));
            }
            {
                int r = wn * 16 + row_off;
                ldsm_x4(Bfh, aBh[bf] + SWOFF(r, cc));
                ldsm_x4(Bfl, aBl[bf] + SWOFF(r, cc));
            }
#pragma unroll
            for (int mi = 0; mi < 4; mi++) {
#pragma unroll
                for (int ni = 0; ni < 2; ni++) {
                    mma16816(acc[mi][ni], Afh[mi], Bfh[ni], Bfh[ni + 2]);
                    mma16816(acc[mi][ni], Afh[mi], Bfl[ni], Bfl[ni + 2]);
                    mma16816(acc[mi][ni], Afl[mi], Bfh[ni], Bfh[ni + 2]);
                }
            }
        }
        __syncthreads();
    }
#undef LOAD_STAGE

    // ---- epilogue: bias + relu (+ hi/lo re-split for SEL 0/1) ----
    const int g = lane >> 2, tg = lane & 3;
#pragma unroll
    for (int mi = 0; mi < 4; mi++) {
#pragma unroll
        for (int ni = 0; ni < 2; ni++) {
            int col = n0 + wn * 16 + ni * 8 + 2 * tg;
            float b0 = bias[col], b1 = bias[col + 1];
#pragma unroll
            for (int h = 0; h < 2; h++) {
                int row = m0 + wm * 64 + mi * 16 + g + h * 8;
                float v0 = acc[mi][ni][2 * h + 0] + b0;
                float v1 = acc[mi][ni][2 * h + 1] + b1;
                v0 = v0 > 0.f ? v0 : 0.f;
                v1 = v1 > 0.f ? v1 : 0.f;
                size_t idx = (size_t)row * N + col;
                if (SEL == 2) {
                    *reinterpret_cast<float2*>(g_xr + idx) = make_float2(v0, v1);
                } else {
                    __nv_bfloat16* Chi = (SEL == 0) ? g_h0hi : g_h1hi;
                    __nv_bfloat16* Clo = (SEL == 0) ? g_h0lo : g_h1lo;
                    __nv_bfloat162 hh, ll;
                    hh.x = __float2bfloat16(v0);
                    hh.y = __float2bfloat16(v1);
                    ll.x = __float2bfloat16(v0 - __bfloat162float(hh.x));
                    ll.y = __float2bfloat16(v1 - __bfloat162float(hh.y));
                    *reinterpret_cast<__nv_bfloat162*>(Chi + idx) = hh;
                    *reinterpret_cast<__nv_bfloat162*>(Clo + idx) = ll;
                }
            }
        }
    }
}

// -------------------- table init (grid-stride, double precision) ------------
__global__ void init_tables(const float* __restrict__ w0,
                            const float* __restrict__ w1)
{
    const double TWO_PI = 6.283185307179586476925286766559;
    const double PI = 3.1415926535897932384626433832795;
    int gtid = blockIdx.x * blockDim.x + threadIdx.x;
    int nthr = gridDim.x * blockDim.x;
    for (int i = gtid; i < 32768; i += nthr) {
        double s, c;
        sincos(-TWO_PI * (double)i / 32768.0, &s, &c);
        g_btw[i] = make_float2((float)c, (float)s);
    }
    for (int i = gtid; i < 255; i += nthr) {
        int v = i + 1;
        int p = 31 - __clz(v);
        int Ns = 1 << p, jm = v - Ns;
        double s, c;
        sincos(-PI * (double)jm / (double)Ns, &s, &c);
        g_stw1[i] = make_float2((float)c, (float)s);
    }
    for (int i = gtid; i < 127; i += nthr) {
        int v = i + 1;
        int p = 31 - __clz(v);
        int Ns = 1 << p, jm = v - Ns;
        double s, c;
        sincos(-PI * (double)jm / (double)Ns, &s, &c);
        g_stw2[i] = make_float2((float)c, (float)s);
    }
    for (int i = gtid; i < 4096; i += nthr) {
        int a = i >> 6, b = i & 63;
        int t = (a * b) & 63;
        double s, c;
        sincos(-TWO_PI * (double)t / 64.0, &s, &c);
        g_dftF[i] = make_float2((float)c, (float)s);
        g_dftI[i] = make_float2((float)(c / 64.0), (float)(-s / 64.0));
    }
    for (int w = gtid; w < 64; w += nthr) {
        double pr = 0, pi = 0, mr = 0, mi = 0;
        for (int m = 0; m < 32; m++) {
            float a = w0[m * 64 + w];
            float b = w1[m * 64 + w];
            double s, c;
            sincos(TWO_PI * (double)m / 32.0, &s, &c);
            double coef = (double)b * fabs((double)a);
            if (a >= 0.0f) { pr += coef * c; pi += coef * s; }
            else           { mr += coef * c; mi += coef * s; }
        }
        g_P[w] = make_float2((float)pr, (float)pi);
        g_M[w] = make_float2((float)mr, (float)mi);
    }
}

// -------------------- per-row forward DFT-64 --------------------------------
__global__ __launch_bounds__(1024)
void fwd_row_dft()
{
    __shared__ float sx[16][64];
    int tid = threadIdx.x;
    int row0 = blockIdx.x << 4;
    for (int i = tid; i < 16 * 64; i += 1024)
        sx[i >> 6][i & 63] = g_xr[(size_t)(row0 + (i >> 6)) * 64 + (i & 63)];
    __syncthreads();
    int r = tid >> 6, k = tid & 63;
    float re = 0.f, im = 0.f;
#pragma unroll 16
    for (int w = 0; w < 64; w++) {
        float2 t = g_dftF[(w << 6) + k];
        float xv = sx[r][w];
        re = fmaf(xv, t.x, re);
        im = fmaf(xv, t.y, im);
    }
    g_bufA[(size_t)(row0 + r) * 64 + k] = make_float2(re, im);
}

// -------------------- batch-axis FFT, step 1 (fs=+1 fwd, -1 inv) ------------
__global__ __launch_bounds__(256)
void fft_b_step1(float fs)
{
    __shared__ float2 s0[8][256];
    __shared__ float2 s1[8][256];
    __shared__ float2 stw[255];
    int tid = threadIdx.x;
    int n1 = blockIdx.x;
    int c0 = blockIdx.y << 3;
    for (int i = tid; i < 255; i += 256) stw[i] = g_stw1[i];
    for (int i = tid; i < 2048; i += 256) {
        int n2 = i >> 3, ch = i & 7;
        s0[ch][n2] = g_bufA[(size_t)(n1 + (n2 << 7)) * 64 + c0 + ch];
    }
    __syncthreads();
    float2 (*src)[256] = s0;
    float2 (*dst)[256] = s1;
#pragma unroll
    for (int p = 0; p < 8; p++) {
        int Ns = 1 << p;
        for (int u = tid; u < 1024; u += 256) {
            int ch = u >> 7, j = u & 127;
            int jm = j & (Ns - 1);
            float2 a = src[ch][j];
            float2 b = src[ch][j + 128];
            float2 tw = stw[Ns - 1 + jm];
            float c = tw.x, s = fs * tw.y;
            float2 bw = make_float2(b.x * c - b.y * s, b.x * s + b.y * c);
            int idxD = ((j - jm) << 1) + jm;
            dst[ch][idxD]      = make_float2(a.x + bw.x, a.y + bw.y);
            dst[ch][idxD + Ns] = make_float2(a.x - bw.x, a.y - bw.y);
        }
        __syncthreads();
        float2 (*tmp)[256] = src; src = dst; dst = tmp;
    }
    for (int i = tid; i < 2048; i += 256) {
        int k2 = i >> 3, ch = i & 7;
        float2 w = g_btw[(n1 * k2) & 32767];
        float c = w.x, s = fs * w.y;
        float2 v = src[ch][k2];
        g_Z[((size_t)k2 * 128 + n1) * 64 + c0 + ch] =
            make_float2(v.x * c - v.y * s, v.x * s + v.y * c);
    }
}

// -------------------- batch-axis FFT, step 2 --------------------------------
__global__ __launch_bounds__(256)
void fft_b_step2(float fs, float scale)
{
    __shared__ float2 s0[8][128];
    __shared__ float2 s1[8][128];
    __shared__ float2 stw[127];
    int tid = threadIdx.x;
    int k2 = blockIdx.x;
    int c0 = blockIdx.y << 3;
    for (int i = tid; i < 127; i += 256) stw[i] = g_stw2[i];
    for (int i = tid; i < 1024; i += 256) {
        int n1 = i >> 3, ch = i & 7;
        s0[ch][n1] = g_Z[((size_t)k2 * 128 + n1) * 64 + c0 + ch];
    }
    __syncthreads();
    float2 (*src)[128] = s0;
    float2 (*dst)[128] = s1;
#pragma unroll
    for (int p = 0; p < 7; p++) {
        int Ns = 1 << p;
        for (int u = tid; u < 512; u += 256) {
            int ch = u >> 6, j = u & 63;
            int jm = j & (Ns - 1);
            float2 a = src[ch][j];
            float2 b = src[ch][j + 64];
            float2 tw = stw[Ns - 1 + jm];
            float c = tw.x, s = fs * tw.y;
            float2 bw = make_float2(b.x * c - b.y * s, b.x * s + b.y * c);
            int idxD = ((j - jm) << 1) + jm;
            dst[ch][idxD]      = make_float2(a.x + bw.x, a.y + bw.y);
            dst[ch][idxD + Ns] = make_float2(a.x - bw.x, a.y - bw.y);
        }
        __syncthreads();
        float2 (*tmp)[128] = src; src = dst; dst = tmp;
    }
    for (int i = tid; i < 1024; i += 256) {
        int k1 = i >> 3, ch = i & 7;
        float2 v = src[ch][k1];
        g_bufB[(size_t)(k2 + (k1 << 8)) * 64 + c0 + ch] =
            make_float2(v.x * scale, v.y * scale);
    }
}

// -------------------- FNO core ---------------------------------------------
__global__ __launch_bounds__(512)
void mid_kernel(const float* __restrict__ lin1W, const float* __restrict__ lin1b,
                const float* __restrict__ lin2W, const float* __restrict__ lin2b)
{
    __shared__ float L1t[64 * 64];
    __shared__ float L2t[64 * 64];
    __shared__ float yre[8][64], yim[8][64];
    __shared__ float tre[8][64], tim[8][64];
    __shared__ float2 sP[64], sM[64];
    int tid = threadIdx.x;
    int row0 = blockIdx.x << 3;
    for (int i = tid; i < 4096; i += 512) {
        int w = i >> 6, o = i & 63;
        L1t[i] = lin1W[(o << 6) + w];
        L2t[i] = lin2W[(o << 6) + w];
    }
    if (tid < 64) { sP[tid] = g_P[tid]; sM[tid] = g_M[tid]; }
    int r = tid >> 6, w = tid & 63;
    float2 xh = g_bufB[(size_t)(row0 + r) * 64 + w];
    __syncthreads();
    {
        float rp = fmaxf(xh.x, 0.f), rn = fmaxf(-xh.x, 0.f);
        float ip = fmaxf(xh.y, 0.f), im2 = fmaxf(-xh.y, 0.f);
        float2 P = sP[w], Mv = sM[w];
        yre[r][w] = rp * P.x - ip * P.y + rn * Mv.x - im2 * Mv.y;
        yim[r][w] = rp * P.y + ip * P.x + rn * Mv.y + im2 * Mv.x;
    }
    __syncthreads();
    int o = w;
    float re = lin1b[o], im = 0.f;
#pragma unroll 16
    for (int ww = 0; ww < 64; ww++) {
        float lw = L1t[(ww << 6) + o];
        re = fmaf(lw, yre[r][ww], re);
        im = fmaf(lw, yim[r][ww], im);
    }
    tre[r][o] = fmaxf(re, 0.f);
    tim[r][o] = fmaxf(im, 0.f);
    __syncthreads();
    re = lin2b[o]; im = 0.f;
#pragma unroll 16
    for (int ww = 0; ww < 64; ww++) {
        float lw = L2t[(ww << 6) + o];
        re = fmaf(lw, tre[r][ww], re);
        im = fmaf(lw, tim[r][ww], im);
    }
    g_bufA[(size_t)(row0 + r) * 64 + o] = make_float2(re, im);
}

// -------------------- inverse row DFT-64 + W_out ----------------------------
__global__ __launch_bounds__(1024)
void out_kernel(const float* __restrict__ Wout, const float* __restrict__ bout,
                float* __restrict__ outp, int interleaved)
{
    __shared__ float Wt[64 * 128];
    __shared__ float2 sz[8][64];
    __shared__ float2 su[8][64];
    int tid = threadIdx.x;
    int row0 = blockIdx.x << 3;
    for (int i = tid; i < 8192; i += 1024) {
        int w = i >> 7, f = i & 127;
        Wt[i] = Wout[(f << 6) + w];
    }
    if (tid < 512) {
        int r = tid >> 6, k = tid & 63;
        sz[r][k] = g_bufB[(size_t)(row0 + r) * 64 + k];
    }
    __syncthreads();
    if (tid < 512) {
        int r = tid >> 6, w = tid & 63;
        float re = 0.f, im = 0.f;
#pragma unroll 16
        for (int k = 0; k < 64; k++) {
            float2 t = g_dftI[(k << 6) + w];
            float2 z = sz[r][k];
            re += z.x * t.x - z.y * t.y;
            im += z.x * t.y + z.y * t.x;
        }
        su[r][w] = make_float2(re, im);
    }
    __syncthreads();
    int r = tid >> 7, f = tid & 127;
    float re = bout[f], im = 0.f;
#pragma unroll 16
    for (int w = 0; w < 64; w++) {
        float lw = Wt[(w << 7) + f];
        float2 u = su[r][w];
        re = fmaf(lw, u.x, re);
        im = fmaf(lw, u.y, im);
    }
    size_t idx = (size_t)(row0 + r) * 128 + f;
    if (interleaved) {
        reinterpret_cast<float2*>(outp)[idx] = make_float2(re, im);
    } else {
        outp[idx] = re;
    }
}

// ---------------------------------------------------------------------------
extern "C" void kernel_launch(void* const* d_in, const int* in_sizes, int n_in,
                              void* d_out, int out_size)
{
    (void)in_sizes; (void)n_in;
    const float* geom  = (const float*)d_in[0];
    const float* W_in  = (const float*)d_in[1];
    const float* b_in  = (const float*)d_in[2];
    const float* W_h1  = (const float*)d_in[3];
    const float* b_h1  = (const float*)d_in[4];
    const float* W_h2  = (const float*)d_in[5];
    const float* b_h2  = (const float*)d_in[6];
    const float* w0    = (const float*)d_in[7];
    const float* w1    = (const float*)d_in[8];
    const float* lin1W = (const float*)d_in[9];
    const float* lin1b = (const float*)d_in[10];
    const float* lin2W = (const float*)d_in[11];
    const float* lin2b = (const float*)d_in[12];
    const float* Wout  = (const float*)d_in[13];
    const float* bout  = (const float*)d_in[14];

    init_tables<<<64, 256>>>(w0, w1);

    // hi/lo bf16 splits of GEMM inputs
    split_kernel<0><<<(NB * 512 / 4) / 256, 256>>>(geom, NB * 512 / 4);
    split_kernel<1><<<(1024 * 512 / 4) / 256, 256>>>(W_in, 1024 * 512 / 4);
    split_kernel<2><<<(512 * 1024 / 4) / 256, 256>>>(W_h1, 512 * 1024 / 4);
    split_kernel<3><<<(64 * 512 / 4) / 256, 256>>>(W_h2, 64 * 512 / 4);

    // MLP encoder on mma.sync bf16 (hi/lo split, fp32 accumulate)
    mma_gemm<0><<<dim3(1024 / 64, NB / 128), 256>>>(b_in, NB, 1024, 512);
    mma_gemm<1><<<dim3(512 / 64, NB / 128), 256>>>(b_h1, NB, 512, 1024);
    mma_gemm<2><<<dim3(1, NB / 128), 256>>>(b_h2, NB, 64, 512);

    // forward fftn
    fwd_row_dft<<<NB / 16, 1024>>>();
    fft_b_step1<<<dim3(128, 8), 256>>>(1.f);
    fft_b_step2<<<dim3(256, 8), 256>>>(1.f, 1.0f);

    // FNO core
    mid_kernel<<<NB / 8, 512>>>(lin1W, lin1b, lin2W, lin2b);

    // inverse batch-axis FFT (conjugated twiddles)
    fft_b_step1<<<dim3(128, 8), 256>>>(-1.f);
    fft_b_step2<<<dim3(256, 8), 256>>>(-1.f, 1.0f / 32768.0f);

    // inverse row DFT-64 + output projection
    int interleaved = (out_size >= 2 * NB * 128) ? 1 : 0;
    out_kernel<<<NB / 8, 1024>>>(Wout, bout, (float*)d_out, interleaved);
}

// round 7
// speedup vs baseline: 2.1619x; 1.1797x over previous
#include <cuda_runtime.h>
#include <cuda_bf16.h>
#include <math.h>
#include <cstdint>

// ---------------------------------------------------------------------------
// FieldPredictionNetwork:  B=32768, G=512, H0=1024, H1=512, W=64, MODES=32, FD=128
// MLP GEMMs: mma.sync bf16 hi/lo split, 3-stage cp.async pipeline.
// FFT: precomputed twiddles; mid/out: coalesced padded weight smem.
// ---------------------------------------------------------------------------

#define NB 32768

// -------------------- scratch (device globals) ------------------------------
__device__ __nv_bfloat16 g_geomhi[NB * 512],  g_geomlo[NB * 512];
__device__ __nv_bfloat16 g_Winhi[1024 * 512], g_Winlo[1024 * 512];
__device__ __nv_bfloat16 g_Wh1hi[512 * 1024], g_Wh1lo[512 * 1024];
__device__ __nv_bfloat16 g_Wh2hi[64 * 512],   g_Wh2lo[64 * 512];
__device__ __nv_bfloat16 g_h0hi[NB * 1024],   g_h0lo[NB * 1024];
__device__ __nv_bfloat16 g_h1hi[NB * 512],    g_h1lo[NB * 512];
__device__ float  g_xr[NB * 64];
__device__ float2 g_bufA[NB * 64];
__device__ float2 g_bufB[NB * 64];
__device__ float2 g_Z[NB * 64];
__device__ float2 g_dftF[64 * 64];
__device__ float2 g_dftI[64 * 64];
__device__ float2 g_P[64];
__device__ float2 g_M[64];
__device__ float2 g_stw1[256];   // stage twiddles FFT-256
__device__ float2 g_stw2[128];   // stage twiddles FFT-128
__device__ float2 g_btw[32768];  // e^{-2 pi i t / 32768}

// -------------------- small PTX wrappers ------------------------------------
__device__ __forceinline__ uint32_t smem_u32(const void* p) {
    uint32_t a;
    asm("{ .reg .u64 t; cvta.to.shared.u64 t, %1; cvt.u32.u64 %0, t; }" : "=r"(a) : "l"(p));
    return a;
}
__device__ __forceinline__ void ldsm_x4(uint32_t* r, uint32_t a) {
    asm volatile("ldmatrix.sync.aligned.m8n8.x4.shared.b16 {%0,%1,%2,%3}, [%4];"
                 : "=r"(r[0]), "=r"(r[1]), "=r"(r[2]), "=r"(r[3]) : "r"(a));
}
__device__ __forceinline__ void mma16816(float* c, const uint32_t* a,
                                         uint32_t b0, uint32_t b1) {
    asm volatile("mma.sync.aligned.m16n8k16.row.col.f32.bf16.bf16.f32 "
                 "{%0,%1,%2,%3}, {%4,%5,%6,%7}, {%8,%9}, {%0,%1,%2,%3};"
                 : "+f"(c[0]), "+f"(c[1]), "+f"(c[2]), "+f"(c[3])
                 : "r"(a[0]), "r"(a[1]), "r"(a[2]), "r"(a[3]), "r"(b0), "r"(b1));
}
__device__ __forceinline__ void cp16(uint32_t dst, const void* src) {
    asm volatile("cp.async.cg.shared.global [%0], [%1], 16;" :: "r"(dst), "l"(src));
}
#define CP_COMMIT()  asm volatile("cp.async.commit_group;" ::: "memory")
#define CP_WAIT(n)   asm volatile("cp.async.wait_group %0;" :: "n"(n) : "memory")

// 16B-chunk XOR swizzle: row r (bf16 row of 32 elems = 4 chunks), chunk cc.
#define SWOFF(r, cc) ((uint32_t)((r) * 64 + (((cc) ^ (((r) >> 1) & 3)) << 4)))

// -------------------- fp32 -> bf16 hi/lo split ------------------------------
template <int SEL>
__global__ void split_kernel(const float* __restrict__ src, int n4)
{
    __nv_bfloat16* hi = (SEL == 0) ? g_geomhi : (SEL == 1) ? g_Winhi : (SEL == 2) ? g_Wh1hi : g_Wh2hi;
    __nv_bfloat16* lo = (SEL == 0) ? g_geomlo : (SEL == 1) ? g_Winlo : (SEL == 2) ? g_Wh1lo : g_Wh2lo;
    int i = blockIdx.x * blockDim.x + threadIdx.x;
    if (i >= n4) return;
    float4 v = reinterpret_cast<const float4*>(src)[i];
    __nv_bfloat16 h0 = __float2bfloat16(v.x), h1 = __float2bfloat16(v.y);
    __nv_bfloat16 h2 = __float2bfloat16(v.z), h3 = __float2bfloat16(v.w);
    __nv_bfloat162 a, b;
    a.x = h0; a.y = h1; b.x = h2; b.y = h3;
    reinterpret_cast<__nv_bfloat162*>(hi)[2 * i]     = a;
    reinterpret_cast<__nv_bfloat162*>(hi)[2 * i + 1] = b;
    a.x = __float2bfloat16(v.x - __bfloat162float(h0));
    a.y = __float2bfloat16(v.y - __bfloat162float(h1));
    b.x = __float2bfloat16(v.z - __bfloat162float(h2));
    b.y = __float2bfloat16(v.w - __bfloat162float(h3));
    reinterpret_cast<__nv_bfloat162*>(lo)[2 * i]     = a;
    reinterpret_cast<__nv_bfloat162*>(lo)[2 * i + 1] = b;
}

// -------------------- mma.sync bf16-split GEMM + bias + relu ----------------
// C[M,N] = relu(A[M,K] @ B[N,K]^T + bias).  CTA 128x64, BK=32, 3-stage
// cp.async pipeline (dynamic smem).  8 warps = 2(m) x 4(n); warp tile 64x16.
template <int SEL>
__global__ void __launch_bounds__(256)
mma_gemm(const float* __restrict__ bias, int M, int N, int K)
{
    const __nv_bfloat16* Ahi = (SEL == 0) ? g_geomhi : (SEL == 1) ? g_h0hi : g_h1hi;
    const __nv_bfloat16* Alo = (SEL == 0) ? g_geomlo : (SEL == 1) ? g_h0lo : g_h1lo;
    const __nv_bfloat16* Bhi = (SEL == 0) ? g_Winhi  : (SEL == 1) ? g_Wh1hi : g_Wh2hi;
    const __nv_bfloat16* Blo = (SEL == 0) ? g_Winlo  : (SEL == 1) ? g_Wh1lo : g_Wh2lo;

    extern __shared__ __align__(16) char dsm[];
    const uint32_t sb = smem_u32(dsm);
    const uint32_t bAh = sb;                 // 3 x 8192
    const uint32_t bAl = sb + 3 * 8192;      // 3 x 8192
    const uint32_t bBh = sb + 6 * 8192;      // 3 x 4096
    const uint32_t bBl = bBh + 3 * 4096;     // 3 x 4096

    const int tid = threadIdx.x;
    const int warp = tid >> 5, lane = tid & 31;
    const int wm = warp >> 2, wn = warp & 3;
    const int m0 = blockIdx.y * 128, n0 = blockIdx.x * 64;

    float acc[4][2][4];
#pragma unroll
    for (int i = 0; i < 4; i++)
#pragma unroll
        for (int j = 0; j < 2; j++)
#pragma unroll
            for (int q = 0; q < 4; q++) acc[i][j][q] = 0.f;

    const int row_off = (lane & 7) | (((lane >> 3) & 1) << 3);
    const int cc_half = lane >> 4;
    const int ldr = tid >> 2, ldc = tid & 3;
    const uint32_t oA0 = SWOFF(ldr, ldc), oA1 = SWOFF(ldr + 64, ldc);
    const int nchunk = K >> 5;

#define LOAD_STAGE(kc, bf) do {                                                 \
        int _k0 = (kc) << 5;                                                    \
        uint32_t _oa = (uint32_t)(bf) * 8192u, _ob = (uint32_t)(bf) * 4096u;    \
        size_t _g0 = (size_t)(m0 + ldr) * K + _k0 + ldc * 8;                    \
        size_t _g1 = (size_t)(m0 + ldr + 64) * K + _k0 + ldc * 8;               \
        cp16(bAh + _oa + oA0, Ahi + _g0);                                       \
        cp16(bAh + _oa + oA1, Ahi + _g1);                                       \
        cp16(bAl + _oa + oA0, Alo + _g0);                                       \
        cp16(bAl + _oa + oA1, Alo + _g1);                                       \
        size_t _gb = (size_t)(n0 + ldr) * K + _k0 + ldc * 8;                    \
        cp16(bBh + _ob + oA0, Bhi + _gb);                                       \
        cp16(bBl + _ob + oA0, Blo + _gb);                                       \
    } while (0)

    LOAD_STAGE(0, 0); CP_COMMIT();
    LOAD_STAGE(1, 1); CP_COMMIT();

    for (int kc = 0; kc < nchunk; kc++) {
        const int bf = kc % 3;
        if (kc + 2 < nchunk) {
            LOAD_STAGE(kc + 2, (kc + 2) % 3);
            CP_COMMIT();
            CP_WAIT(2);
        } else if (kc + 1 < nchunk) {
            CP_WAIT(1);
        } else {
            CP_WAIT(0);
        }
        __syncthreads();
        const uint32_t oa = (uint32_t)bf * 8192u, ob = (uint32_t)bf * 4096u;
#pragma unroll
        for (int s = 0; s < 2; s++) {
            const int cc = 2 * s + cc_half;
            uint32_t Afh[4][4], Afl[4][4], Bfh[4], Bfl[4];
#pragma unroll
            for (int mi = 0; mi < 4; mi++) {
                int r = wm * 64 + mi * 16 + row_off;
                ldsm_x4(Afh[mi], bAh + oa + SWOFF(r, cc));
                ldsm_x4(Afl[mi], bAl + oa + SWOFF(r, cc));
            }
            {
                int r = wn * 16 + row_off;
                ldsm_x4(Bfh, bBh + ob + SWOFF(r, cc));
                ldsm_x4(Bfl, bBl + ob + SWOFF(r, cc));
            }
#pragma unroll
            for (int mi = 0; mi < 4; mi++) {
#pragma unroll
                for (int ni = 0; ni < 2; ni++) {
                    mma16816(acc[mi][ni], Afh[mi], Bfh[ni], Bfh[ni + 2]);
                    mma16816(acc[mi][ni], Afh[mi], Bfl[ni], Bfl[ni + 2]);
                    mma16816(acc[mi][ni], Afl[mi], Bfh[ni], Bfh[ni + 2]);
                }
            }
        }
        __syncthreads();
    }
#undef LOAD_STAGE

    // ---- epilogue: bias + relu (+ hi/lo re-split for SEL 0/1) ----
    const int g = lane >> 2, tg = lane & 3;
#pragma unroll
    for (int mi = 0; mi < 4; mi++) {
#pragma unroll
        for (int ni = 0; ni < 2; ni++) {
            int col = n0 + wn * 16 + ni * 8 + 2 * tg;
            float b0 = bias[col], b1 = bias[col + 1];
#pragma unroll
            for (int h = 0; h < 2; h++) {
                int row = m0 + wm * 64 + mi * 16 + g + h * 8;
                float v0 = acc[mi][ni][2 * h + 0] + b0;
                float v1 = acc[mi][ni][2 * h + 1] + b1;
                v0 = v0 > 0.f ? v0 : 0.f;
                v1 = v1 > 0.f ? v1 : 0.f;
                size_t idx = (size_t)row * N + col;
                if (SEL == 2) {
                    *reinterpret_cast<float2*>(g_xr + idx) = make_float2(v0, v1);
                } else {
                    __nv_bfloat16* Chi = (SEL == 0) ? g_h0hi : g_h1hi;
                    __nv_bfloat16* Clo = (SEL == 0) ? g_h0lo : g_h1lo;
                    __nv_bfloat162 hh, ll;
                    hh.x = __float2bfloat16(v0);
                    hh.y = __float2bfloat16(v1);
                    ll.x = __float2bfloat16(v0 - __bfloat162float(hh.x));
                    ll.y = __float2bfloat16(v1 - __bfloat162float(hh.y));
                    *reinterpret_cast<__nv_bfloat162*>(Chi + idx) = hh;
                    *reinterpret_cast<__nv_bfloat162*>(Clo + idx) = ll;
                }
            }
        }
    }
}

// -------------------- table init (grid-stride, double precision) ------------
__global__ void init_tables(const float* __restrict__ w0,
                            const float* __restrict__ w1)
{
    const double TWO_PI = 6.283185307179586476925286766559;
    const double PI = 3.1415926535897932384626433832795;
    int gtid = blockIdx.x * blockDim.x + threadIdx.x;
    int nthr = gridDim.x * blockDim.x;
    for (int i = gtid; i < 32768; i += nthr) {
        double s, c;
        sincos(-TWO_PI * (double)i / 32768.0, &s, &c);
        g_btw[i] = make_float2((float)c, (float)s);
    }
    for (int i = gtid; i < 255; i += nthr) {
        int v = i + 1;
        int p = 31 - __clz(v);
        int Ns = 1 << p, jm = v - Ns;
        double s, c;
        sincos(-PI * (double)jm / (double)Ns, &s, &c);
        g_stw1[i] = make_float2((float)c, (float)s);
    }
    for (int i = gtid; i < 127; i += nthr) {
        int v = i + 1;
        int p = 31 - __clz(v);
        int Ns = 1 << p, jm = v - Ns;
        double s, c;
        sincos(-PI * (double)jm / (double)Ns, &s, &c);
        g_stw2[i] = make_float2((float)c, (float)s);
    }
    for (int i = gtid; i < 4096; i += nthr) {
        int a = i >> 6, b = i & 63;
        int t = (a * b) & 63;
        double s, c;
        sincos(-TWO_PI * (double)t / 64.0, &s, &c);
        g_dftF[i] = make_float2((float)c, (float)s);
        g_dftI[i] = make_float2((float)(c / 64.0), (float)(-s / 64.0));
    }
    for (int w = gtid; w < 64; w += nthr) {
        double pr = 0, pi = 0, mr = 0, mi = 0;
        for (int m = 0; m < 32; m++) {
            float a = w0[m * 64 + w];
            float b = w1[m * 64 + w];
            double s, c;
            sincos(TWO_PI * (double)m / 32.0, &s, &c);
            double coef = (double)b * fabs((double)a);
            if (a >= 0.0f) { pr += coef * c; pi += coef * s; }
            else           { mr += coef * c; mi += coef * s; }
        }
        g_P[w] = make_float2((float)pr, (float)pi);
        g_M[w] = make_float2((float)mr, (float)mi);
    }
}

// -------------------- per-row forward DFT-64 --------------------------------
__global__ __launch_bounds__(1024)
void fwd_row_dft()
{
    __shared__ float sx[16][64];
    int tid = threadIdx.x;
    int row0 = blockIdx.x << 4;
    for (int i = tid; i < 16 * 64; i += 1024)
        sx[i >> 6][i & 63] = g_xr[(size_t)(row0 + (i >> 6)) * 64 + (i & 63)];
    __syncthreads();
    int r = tid >> 6, k = tid & 63;
    float re = 0.f, im = 0.f;
#pragma unroll 16
    for (int w = 0; w < 64; w++) {
        float2 t = g_dftF[(w << 6) + k];
        float xv = sx[r][w];
        re = fmaf(xv, t.x, re);
        im = fmaf(xv, t.y, im);
    }
    g_bufA[(size_t)(row0 + r) * 64 + k] = make_float2(re, im);
}

// -------------------- batch-axis FFT, step 1 (fs=+1 fwd, -1 inv) ------------
__global__ __launch_bounds__(256)
void fft_b_step1(float fs)
{
    __shared__ float2 s0[8][256];
    __shared__ float2 s1[8][256];
    __shared__ float2 stw[255];
    int tid = threadIdx.x;
    int n1 = blockIdx.x;
    int c0 = blockIdx.y << 3;
    for (int i = tid; i < 255; i += 256) stw[i] = g_stw1[i];
    for (int i = tid; i < 2048; i += 256) {
        int n2 = i >> 3, ch = i & 7;
        s0[ch][n2] = g_bufA[(size_t)(n1 + (n2 << 7)) * 64 + c0 + ch];
    }
    __syncthreads();
    float2 (*src)[256] = s0;
    float2 (*dst)[256] = s1;
#pragma unroll
    for (int p = 0; p < 8; p++) {
        int Ns = 1 << p;
        for (int u = tid; u < 1024; u += 256) {
            int ch = u >> 7, j = u & 127;
            int jm = j & (Ns - 1);
            float2 a = src[ch][j];
            float2 b = src[ch][j + 128];
            float2 tw = stw[Ns - 1 + jm];
            float c = tw.x, s = fs * tw.y;
            float2 bw = make_float2(b.x * c - b.y * s, b.x * s + b.y * c);
            int idxD = ((j - jm) << 1) + jm;
            dst[ch][idxD]      = make_float2(a.x + bw.x, a.y + bw.y);
            dst[ch][idxD + Ns] = make_float2(a.x - bw.x, a.y - bw.y);
        }
        __syncthreads();
        float2 (*tmp)[256] = src; src = dst; dst = tmp;
    }
    for (int i = tid; i < 2048; i += 256) {
        int k2 = i >> 3, ch = i & 7;
        float2 w = g_btw[(n1 * k2) & 32767];
        float c = w.x, s = fs * w.y;
        float2 v = src[ch][k2];
        g_Z[((size_t)k2 * 128 + n1) * 64 + c0 + ch] =
            make_float2(v.x * c - v.y * s, v.x * s + v.y * c);
    }
}

// -------------------- batch-axis FFT, step 2 --------------------------------
__global__ __launch_bounds__(256)
void fft_b_step2(float fs, float scale)
{
    __shared__ float2 s0[8][128];
    __shared__ float2 s1[8][128];
    __shared__ float2 stw[127];
    int tid = threadIdx.x;
    int k2 = blockIdx.x;
    int c0 = blockIdx.y << 3;
    for (int i = tid; i < 127; i += 256) stw[i] = g_stw2[i];
    for (int i = tid; i < 1024; i += 256) {
        int n1 = i >> 3, ch = i & 7;
        s0[ch][n1] = g_Z[((size_t)k2 * 128 + n1) * 64 + c0 + ch];
    }
    __syncthreads();
    float2 (*src)[128] = s0;
    float2 (*dst)[128] = s1;
#pragma unroll
    for (int p = 0; p < 7; p++) {
        int Ns = 1 << p;
        for (int u = tid; u < 512; u += 256) {
            int ch = u >> 6, j = u & 63;
            int jm = j & (Ns - 1);
            float2 a = src[ch][j];
            float2 b = src[ch][j + 64];
            float2 tw = stw[Ns - 1 + jm];
            float c = tw.x, s = fs * tw.y;
            float2 bw = make_float2(b.x * c - b.y * s, b.x * s + b.y * c);
            int idxD = ((j - jm) << 1) + jm;
            dst[ch][idxD]      = make_float2(a.x + bw.x, a.y + bw.y);
            dst[ch][idxD + Ns] = make_float2(a.x - bw.x, a.y - bw.y);
        }
        __syncthreads();
        float2 (*tmp)[128] = src; src = dst; dst = tmp;
    }
    for (int i = tid; i < 1024; i += 256) {
        int k1 = i >> 3, ch = i & 7;
        float2 v = src[ch][k1];
        g_bufB[(size_t)(k2 + (k1 << 8)) * 64 + c0 + ch] =
            make_float2(v.x * scale, v.y * scale);
    }
}

// -------------------- FNO core (16 rows/block, padded weights) --------------
__global__ __launch_bounds__(1024)
void mid_kernel(const float* __restrict__ lin1W, const float* __restrict__ lin1b,
                const float* __restrict__ lin2W, const float* __restrict__ lin2b)
{
    __shared__ float L1t[64 * 65];   // natural [o][w], pad 65 (conflict-free)
    __shared__ float L2t[64 * 65];
    __shared__ float yre[16][64], yim[16][64];
    __shared__ float2 sP[64], sM[64];
    int tid = threadIdx.x;
    int row0 = blockIdx.x << 4;
    for (int i = tid; i < 4096; i += 1024) {
        int o = i >> 6, w = i & 63;
        L1t[o * 65 + w] = lin1W[i];
        L2t[o * 65 + w] = lin2W[i];
    }
    if (tid < 64) { sP[tid] = g_P[tid]; sM[tid] = g_M[tid]; }
    int r = tid >> 6, w = tid & 63;
    float2 xh = g_bufB[(size_t)(row0 + r) * 64 + w];
    __syncthreads();
    {
        float rp = fmaxf(xh.x, 0.f), rn = fmaxf(-xh.x, 0.f);
        float ip = fmaxf(xh.y, 0.f), im2 = fmaxf(-xh.y, 0.f);
        float2 P = sP[w], Mv = sM[w];
        yre[r][w] = rp * P.x - ip * P.y + rn * Mv.x - im2 * Mv.y;
        yim[r][w] = rp * P.y + ip * P.x + rn * Mv.y + im2 * Mv.x;
    }
    __syncthreads();
    int o = w;
    float re = lin1b[o], im = 0.f;
#pragma unroll 16
    for (int ww = 0; ww < 64; ww++) {
        float lw = L1t[o * 65 + ww];
        re = fmaf(lw, yre[r][ww], re);
        im = fmaf(lw, yim[r][ww], im);
    }
    re = fmaxf(re, 0.f);
    im = fmaxf(im, 0.f);
    __syncthreads();                 // all reads of yre/yim done
    yre[r][o] = re;
    yim[r][o] = im;
    __syncthreads();
    re = lin2b[o]; im = 0.f;
#pragma unroll 16
    for (int ww = 0; ww < 64; ww++) {
        float lw = L2t[o * 65 + ww];
        re = fmaf(lw, yre[r][ww], re);
        im = fmaf(lw, yim[r][ww], im);
    }
    g_bufA[(size_t)(row0 + r) * 64 + o] = make_float2(re, im);
}

// -------------------- inverse row DFT-64 + W_out (16 rows/block) ------------
__global__ __launch_bounds__(1024)
void out_kernel(const float* __restrict__ Wout, const float* __restrict__ bout,
                float* __restrict__ outp, int interleaved)
{
    __shared__ float Wt[128 * 65];   // natural [f][w], pad 65
    __shared__ float2 szu[16][64];   // sz, then reused as su
    int tid = threadIdx.x;
    int row0 = blockIdx.x << 4;
    for (int i = tid; i < 8192; i += 1024) {
        int f = i >> 6, w = i & 63;
        Wt[f * 65 + w] = Wout[i];
    }
    {
        int r = tid >> 6, k = tid & 63;
        szu[r][k] = g_bufB[(size_t)(row0 + r) * 64 + k];
    }
    __syncthreads();
    // phase 1: inverse row DFT-64 (register-staged, reuse szu)
    float ure, uim;
    {
        int r = tid >> 6, w = tid & 63;
        float re = 0.f, im = 0.f;
#pragma unroll 16
        for (int k = 0; k < 64; k++) {
            float2 t = g_dftI[(k << 6) + w];
            float2 z = szu[r][k];
            re += z.x * t.x - z.y * t.y;
            im += z.x * t.y + z.y * t.x;
        }
        ure = re; uim = im;
    }
    __syncthreads();
    {
        int r = tid >> 6, w = tid & 63;
        szu[r][w] = make_float2(ure, uim);
    }
    __syncthreads();
    // phase 2: W_out projection, 2048 outputs / 1024 threads
#pragma unroll
    for (int it = 0; it < 2; it++) {
        int idx = it * 1024 + tid;
        int r = idx >> 7, f = idx & 127;
        float re = bout[f], im = 0.f;
#pragma unroll 16
        for (int w = 0; w < 64; w++) {
            float lw = Wt[f * 65 + w];
            float2 u = szu[r][w];
            re = fmaf(lw, u.x, re);
            im = fmaf(lw, u.y, im);
        }
        size_t oidx = (size_t)(row0 + r) * 128 + f;
        if (interleaved) {
            reinterpret_cast<float2*>(outp)[oidx] = make_float2(re, im);
        } else {
            outp[oidx] = re;
        }
    }
}

// ---------------------------------------------------------------------------
extern "C" void kernel_launch(void* const* d_in, const int* in_sizes, int n_in,
                              void* d_out, int out_size)
{
    (void)in_sizes; (void)n_in;
    const float* geom  = (const float*)d_in[0];
    const float* W_in  = (const float*)d_in[1];
    const float* b_in  = (const float*)d_in[2];
    const float* W_h1  = (const float*)d_in[3];
    const float* b_h1  = (const float*)d_in[4];
    const float* W_h2  = (const float*)d_in[5];
    const float* b_h2  = (const float*)d_in[6];
    const float* w0    = (const float*)d_in[7];
    const float* w1    = (const float*)d_in[8];
    const float* lin1W = (const float*)d_in[9];
    const float* lin1b = (const float*)d_in[10];
    const float* lin2W = (const float*)d_in[11];
    const float* lin2b = (const float*)d_in[12];
    const float* Wout  = (const float*)d_in[13];
    const float* bout  = (const float*)d_in[14];

    const int GSM = 3 * (8192 + 8192 + 4096 + 4096);   // 73728 bytes
    cudaFuncSetAttribute(mma_gemm<0>, cudaFuncAttributeMaxDynamicSharedMemorySize, GSM);
    cudaFuncSetAttribute(mma_gemm<1>, cudaFuncAttributeMaxDynamicSharedMemorySize, GSM);
    cudaFuncSetAttribute(mma_gemm<2>, cudaFuncAttributeMaxDynamicSharedMemorySize, GSM);

    init_tables<<<64, 256>>>(w0, w1);

    // splits + GEMMs (ordered so mma_gemm<0> lands in the ncu capture slot)
    split_kernel<0><<<(NB * 512 / 4) / 256, 256>>>(geom, NB * 512 / 4);
    split_kernel<1><<<(1024 * 512 / 4) / 256, 256>>>(W_in, 1024 * 512 / 4);
    mma_gemm<0><<<dim3(1024 / 64, NB / 128), 256, GSM>>>(b_in, NB, 1024, 512);
    split_kernel<2><<<(512 * 1024 / 4) / 256, 256>>>(W_h1, 512 * 1024 / 4);
    mma_gemm<1><<<dim3(512 / 64, NB / 128), 256, GSM>>>(b_h1, NB, 512, 1024);
    split_kernel<3><<<(64 * 512 / 4) / 256, 256>>>(W_h2, 64 * 512 / 4);
    mma_gemm<2><<<dim3(1, NB / 128), 256, GSM>>>(b_h2, NB, 64, 512);

    // forward fftn
    fwd_row_dft<<<NB / 16, 1024>>>();
    fft_b_step1<<<dim3(128, 8), 256>>>(1.f);
    fft_b_step2<<<dim3(256, 8), 256>>>(1.f, 1.0f);

    // FNO core
    mid_kernel<<<NB / 16, 1024>>>(lin1W, lin1b, lin2W, lin2b);

    // inverse batch-axis FFT (conjugated twiddles)
    fft_b_step1<<<dim3(128, 8), 256>>>(-1.f);
    fft_b_step2<<<dim3(256, 8), 256>>>(-1.f, 1.0f / 32768.0f);

    // inverse row DFT-64 + output projection
    int interleaved = (out_size >= 2 * NB * 128) ? 1 : 0;
    out_kernel<<<NB / 16, 1024>>>(Wout, bout, (float*)d_out, interleaved);
}

// round 9
// speedup vs baseline: 2.2962x; 1.0621x over previous
#include <cuda_runtime.h>
#include <cuda_bf16.h>
#include <math.h>
#include <cstdint>

// ---------------------------------------------------------------------------
// FieldPredictionNetwork:  B=32768, G=512, H0=1024, H1=512, W=64, MODES=32, FD=128
// MLP GEMMs: mma.sync bf16 hi/lo split, CTA 128x128, 3-stage cp.async.
// FFT: precomputed twiddles; mid/out: coalesced padded weight smem.
// ---------------------------------------------------------------------------

#define NB 32768

// -------------------- scratch (device globals) ------------------------------
__device__ __nv_bfloat16 g_geomhi[NB * 512],  g_geomlo[NB * 512];
__device__ __nv_bfloat16 g_Winhi[1024 * 512], g_Winlo[1024 * 512];
__device__ __nv_bfloat16 g_Wh1hi[512 * 1024], g_Wh1lo[512 * 1024];
__device__ __nv_bfloat16 g_Wh2hi[64 * 512],   g_Wh2lo[64 * 512];
__device__ __nv_bfloat16 g_h0hi[NB * 1024],   g_h0lo[NB * 1024];
__device__ __nv_bfloat16 g_h1hi[NB * 512],    g_h1lo[NB * 512];
__device__ float  g_xr[NB * 64];
__device__ float2 g_bufA[NB * 64];
__device__ float2 g_bufB[NB * 64];
__device__ float2 g_Z[NB * 64];
__device__ float2 g_dftF[64 * 64];
__device__ float2 g_dftI[64 * 64];
__device__ float2 g_P[64];
__device__ float2 g_M[64];
__device__ float2 g_stw1[256];
__device__ float2 g_stw2[128];
__device__ float2 g_btw[32768];

// -------------------- small PTX wrappers ------------------------------------
__device__ __forceinline__ uint32_t smem_u32(const void* p) {
    uint32_t a;
    asm("{ .reg .u64 t; cvta.to.shared.u64 t, %1; cvt.u32.u64 %0, t; }" : "=r"(a) : "l"(p));
    return a;
}
__device__ __forceinline__ void ldsm_x4(uint32_t* r, uint32_t a) {
    asm volatile("ldmatrix.sync.aligned.m8n8.x4.shared.b16 {%0,%1,%2,%3}, [%4];"
                 : "=r"(r[0]), "=r"(r[1]), "=r"(r[2]), "=r"(r[3]) : "r"(a));
}
__device__ __forceinline__ void mma16816(float* c, const uint32_t* a,
                                         uint32_t b0, uint32_t b1) {
    asm volatile("mma.sync.aligned.m16n8k16.row.col.f32.bf16.bf16.f32 "
                 "{%0,%1,%2,%3}, {%4,%5,%6,%7}, {%8,%9}, {%0,%1,%2,%3};"
                 : "+f"(c[0]), "+f"(c[1]), "+f"(c[2]), "+f"(c[3])
                 : "r"(a[0]), "r"(a[1]), "r"(a[2]), "r"(a[3]), "r"(b0), "r"(b1));
}
__device__ __forceinline__ void cp16(uint32_t dst, const void* src) {
    asm volatile("cp.async.cg.shared.global [%0], [%1], 16;" :: "r"(dst), "l"(src));
}
#define CP_COMMIT()  asm volatile("cp.async.commit_group;" ::: "memory")
#define CP_WAIT(n)   asm volatile("cp.async.wait_group %0;" :: "n"(n) : "memory")

// 16B-chunk XOR swizzle: row r (bf16 row of 32 elems = 4 chunks), chunk cc.
#define SWOFF(r, cc) ((uint32_t)((r) * 64 + (((cc) ^ (((r) >> 1) & 3)) << 4)))

// -------------------- fp32 -> bf16 hi/lo split ------------------------------
template <int SEL>
__global__ void split_kernel(const float* __restrict__ src, int n4)
{
    __nv_bfloat16* hi = (SEL == 0) ? g_geomhi : (SEL == 1) ? g_Winhi : (SEL == 2) ? g_Wh1hi : g_Wh2hi;
    __nv_bfloat16* lo = (SEL == 0) ? g_geomlo : (SEL == 1) ? g_Winlo : (SEL == 2) ? g_Wh1lo : g_Wh2lo;
    int i = blockIdx.x * blockDim.x + threadIdx.x;
    if (i >= n4) return;
    float4 v = reinterpret_cast<const float4*>(src)[i];
    __nv_bfloat16 h0 = __float2bfloat16(v.x), h1 = __float2bfloat16(v.y);
    __nv_bfloat16 h2 = __float2bfloat16(v.z), h3 = __float2bfloat16(v.w);
    __nv_bfloat162 a, b;
    a.x = h0; a.y = h1; b.x = h2; b.y = h3;
    reinterpret_cast<__nv_bfloat162*>(hi)[2 * i]     = a;
    reinterpret_cast<__nv_bfloat162*>(hi)[2 * i + 1] = b;
    a.x = __float2bfloat16(v.x - __bfloat162float(h0));
    a.y = __float2bfloat16(v.y - __bfloat162float(h1));
    b.x = __float2bfloat16(v.z - __bfloat162float(h2));
    b.y = __float2bfloat16(v.w - __bfloat162float(h3));
    reinterpret_cast<__nv_bfloat162*>(lo)[2 * i]     = a;
    reinterpret_cast<__nv_bfloat162*>(lo)[2 * i + 1] = b;
}

// -------------------- mma.sync bf16-split GEMM + bias + relu ----------------
// C[M,N] = relu(A[M,K] @ B[N,K]^T + bias).  CTA 128 x BN, BK=32, 3-stage
// cp.async.  8 warps = 2(m) x 4(n); warp tile 64 x (BN/4).
template <int BN, int SEL>
__global__ void __launch_bounds__(256, 2)
mma_gemm(const float* __restrict__ bias, int M, int N, int K)
{
    const __nv_bfloat16* Ahi = (SEL == 0) ? g_geomhi : (SEL == 1) ? g_h0hi : g_h1hi;
    const __nv_bfloat16* Alo = (SEL == 0) ? g_geomlo : (SEL == 1) ? g_h0lo : g_h1lo;
    const __nv_bfloat16* Bhi = (SEL == 0) ? g_Winhi  : (SEL == 1) ? g_Wh1hi : g_Wh2hi;
    const __nv_bfloat16* Blo = (SEL == 0) ? g_Winlo  : (SEL == 1) ? g_Wh1lo : g_Wh2lo;

    constexpr int ASTG = 8192;          // 128 rows x 32 bf16
    constexpr int BSTG = BN * 64;       // BN rows x 32 bf16
    constexpr int WN   = BN / 4;        // warp n width (16 or 32)
    constexpr int NFR  = WN / 16;       // B ldsm_x4 per hi/lo: 1 (BN=64) or 2 (BN=128)
    constexpr int NNI  = WN / 8;        // n8 frags per warp: 2 (BN=64) or 4 (BN=128)

    extern __shared__ __align__(16) char dsm[];
    const uint32_t sb  = smem_u32(dsm);
    const uint32_t bAh = sb;
    const uint32_t bAl = sb + 3 * ASTG;
    const uint32_t bBh = sb + 6 * ASTG;
    const uint32_t bBl = bBh + 3 * BSTG;

    const int tid = threadIdx.x;
    const int warp = tid >> 5, lane = tid & 31;
    const int wm = warp >> 2, wn = warp & 3;
    const int m0 = blockIdx.y * 128, n0 = blockIdx.x * BN;

    float acc[4][NNI][4];
#pragma unroll
    for (int i = 0; i < 4; i++)
#pragma unroll
        for (int j = 0; j < NNI; j++)
#pragma unroll
            for (int q = 0; q < 4; q++) acc[i][j][q] = 0.f;

    const int row_off = (lane & 7) | (((lane >> 3) & 1) << 3);
    const int cc_half = lane >> 4;
    const int ldr = tid >> 2, ldc = tid & 3;
    const uint32_t oA0 = SWOFF(ldr, ldc), oA1 = SWOFF(ldr + 64, ldc);
    const int nchunk = K >> 5;

#define LOAD_STAGE(kc, bf) do {                                                 \
        int _k0 = (kc) << 5;                                                    \
        uint32_t _oa = (uint32_t)(bf) * ASTG, _ob = (uint32_t)(bf) * BSTG;      \
        size_t _g0 = (size_t)(m0 + ldr) * K + _k0 + ldc * 8;                    \
        size_t _g1 = (size_t)(m0 + ldr + 64) * K + _k0 + ldc * 8;               \
        cp16(bAh + _oa + oA0, Ahi + _g0);                                       \
        cp16(bAh + _oa + oA1, Ahi + _g1);                                       \
        cp16(bAl + _oa + oA0, Alo + _g0);                                       \
        cp16(bAl + _oa + oA1, Alo + _g1);                                       \
        size_t _gb0 = (size_t)(n0 + ldr) * K + _k0 + ldc * 8;                   \
        cp16(bBh + _ob + oA0, Bhi + _gb0);                                      \
        cp16(bBl + _ob + oA0, Blo + _gb0);                                      \
        if (BN == 128) {                                                        \
            size_t _gb1 = (size_t)(n0 + ldr + 64) * K + _k0 + ldc * 8;          \
            cp16(bBh + _ob + oA1, Bhi + _gb1);                                  \
            cp16(bBl + _ob + oA1, Blo + _gb1);                                  \
        }                                                                       \
    } while (0)

    LOAD_STAGE(0, 0); CP_COMMIT();
    LOAD_STAGE(1, 1); CP_COMMIT();

    for (int kc = 0; kc < nchunk; kc++) {
        const int bf = kc % 3;
        if (kc + 2 < nchunk) {
            LOAD_STAGE(kc + 2, (kc + 2) % 3);
            CP_COMMIT();
            CP_WAIT(2);
        } else if (kc + 1 < nchunk) {
            CP_WAIT(1);
        } else {
            CP_WAIT(0);
        }
        __syncthreads();
        const uint32_t oa = (uint32_t)bf * ASTG, ob = (uint32_t)bf * BSTG;
#pragma unroll
        for (int s = 0; s < 2; s++) {
            const int cc = 2 * s + cc_half;
            uint32_t Afh[4][4], Afl[4][4], Bfh[4 * NFR], Bfl[4 * NFR];
#pragma unroll
            for (int mi = 0; mi < 4; mi++) {
                int r = wm * 64 + mi * 16 + row_off;
                ldsm_x4(Afh[mi], bAh + oa + SWOFF(r, cc));
                ldsm_x4(Afl[mi], bAl + oa + SWOFF(r, cc));
            }
#pragma unroll
            for (int f = 0; f < NFR; f++) {
                int r = wn * WN + f * 16 + row_off;
                ldsm_x4(Bfh + 4 * f, bBh + ob + SWOFF(r, cc));
                ldsm_x4(Bfl + 4 * f, bBl + ob + SWOFF(r, cc));
            }
#pragma unroll
            for (int mi = 0; mi < 4; mi++) {
#pragma unroll
                for (int ni = 0; ni < NNI; ni++) {
                    const int q = (ni >> 1) * 4 + (ni & 1);
                    mma16816(acc[mi][ni], Afh[mi], Bfh[q], Bfh[q + 2]);
                    mma16816(acc[mi][ni], Afh[mi], Bfl[q], Bfl[q + 2]);
                    mma16816(acc[mi][ni], Afl[mi], Bfh[q], Bfh[q + 2]);
                }
            }
        }
        __syncthreads();
    }
#undef LOAD_STAGE

    // ---- epilogue: bias + relu (+ hi/lo re-split for SEL 0/1) ----
    const int g = lane >> 2, tg = lane & 3;
#pragma unroll
    for (int mi = 0; mi < 4; mi++) {
#pragma unroll
        for (int ni = 0; ni < NNI; ni++) {
            int col = n0 + wn * WN + ni * 8 + 2 * tg;
            float b0 = bias[col], b1 = bias[col + 1];
#pragma unroll
            for (int h = 0; h < 2; h++) {
                int row = m0 + wm * 64 + mi * 16 + g + h * 8;
                float v0 = acc[mi][ni][2 * h + 0] + b0;
                float v1 = acc[mi][ni][2 * h + 1] + b1;
                v0 = v0 > 0.f ? v0 : 0.f;
                v1 = v1 > 0.f ? v1 : 0.f;
                size_t idx = (size_t)row * N + col;
                if (SEL == 2) {
                    *reinterpret_cast<float2*>(g_xr + idx) = make_float2(v0, v1);
                } else {
                    __nv_bfloat16* Chi = (SEL == 0) ? g_h0hi : g_h1hi;
                    __nv_bfloat16* Clo = (SEL == 0) ? g_h0lo : g_h1lo;
                    __nv_bfloat162 hh, ll;
                    hh.x = __float2bfloat16(v0);
                    hh.y = __float2bfloat16(v1);
                    ll.x = __float2bfloat16(v0 - __bfloat162float(hh.x));
                    ll.y = __float2bfloat16(v1 - __bfloat162float(hh.y));
                    *reinterpret_cast<__nv_bfloat162*>(Chi + idx) = hh;
                    *reinterpret_cast<__nv_bfloat162*>(Clo + idx) = ll;
                }
            }
        }
    }
}

// -------------------- table init (grid-stride, double precision) ------------
__global__ void init_tables(const float* __restrict__ w0,
                            const float* __restrict__ w1)
{
    const double TWO_PI = 6.283185307179586476925286766559;
    const double PI = 3.1415926535897932384626433832795;
    int gtid = blockIdx.x * blockDim.x + threadIdx.x;
    int nthr = gridDim.x * blockDim.x;
    for (int i = gtid; i < 32768; i += nthr) {
        double s, c;
        sincos(-TWO_PI * (double)i / 32768.0, &s, &c);
        g_btw[i] = make_float2((float)c, (float)s);
    }
    for (int i = gtid; i < 255; i += nthr) {
        int v = i + 1;
        int p = 31 - __clz(v);
        int Ns = 1 << p, jm = v - Ns;
        double s, c;
        sincos(-PI * (double)jm / (double)Ns, &s, &c);
        g_stw1[i] = make_float2((float)c, (float)s);
    }
    for (int i = gtid; i < 127; i += nthr) {
        int v = i + 1;
        int p = 31 - __clz(v);
        int Ns = 1 << p, jm = v - Ns;
        double s, c;
        sincos(-PI * (double)jm / (double)Ns, &s, &c);
        g_stw2[i] = make_float2((float)c, (float)s);
    }
    for (int i = gtid; i < 4096; i += nthr) {
        int a = i >> 6, b = i & 63;
        int t = (a * b) & 63;
        double s, c;
        sincos(-TWO_PI * (double)t / 64.0, &s, &c);
        g_dftF[i] = make_float2((float)c, (float)s);
        g_dftI[i] = make_float2((float)(c / 64.0), (float)(-s / 64.0));
    }
    for (int w = gtid; w < 64; w += nthr) {
        double pr = 0, pi = 0, mr = 0, mi = 0;
        for (int m = 0; m < 32; m++) {
            float a = w0[m * 64 + w];
            float b = w1[m * 64 + w];
            double s, c;
            sincos(TWO_PI * (double)m / 32.0, &s, &c);
            double coef = (double)b * fabs((double)a);
            if (a >= 0.0f) { pr += coef * c; pi += coef * s; }
            else           { mr += coef * c; mi += coef * s; }
        }
        g_P[w] = make_float2((float)pr, (float)pi);
        g_M[w] = make_float2((float)mr, (float)mi);
    }
}

// -------------------- per-row forward DFT-64 --------------------------------
__global__ __launch_bounds__(1024)
void fwd_row_dft()
{
    __shared__ float sx[16][64];
    int tid = threadIdx.x;
    int row0 = blockIdx.x << 4;
    for (int i = tid; i < 16 * 64; i += 1024)
        sx[i >> 6][i & 63] = g_xr[(size_t)(row0 + (i >> 6)) * 64 + (i & 63)];
    __syncthreads();
    int r = tid >> 6, k = tid & 63;
    float re = 0.f, im = 0.f;
#pragma unroll 16
    for (int w = 0; w < 64; w++) {
        float2 t = g_dftF[(w << 6) + k];
        float xv = sx[r][w];
        re = fmaf(xv, t.x, re);
        im = fmaf(xv, t.y, im);
    }
    g_bufA[(size_t)(row0 + r) * 64 + k] = make_float2(re, im);
}

// -------------------- batch-axis FFT, step 1 (fs=+1 fwd, -1 inv) ------------
__global__ __launch_bounds__(256)
void fft_b_step1(float fs)
{
    __shared__ float2 s0[8][256];
    __shared__ float2 s1[8][256];
    __shared__ float2 stw[255];
    int tid = threadIdx.x;
    int n1 = blockIdx.x;
    int c0 = blockIdx.y << 3;
    for (int i = tid; i < 255; i += 256) stw[i] = g_stw1[i];
    for (int i = tid; i < 2048; i += 256) {
        int n2 = i >> 3, ch = i & 7;
        s0[ch][n2] = g_bufA[(size_t)(n1 + (n2 << 7)) * 64 + c0 + ch];
    }
    __syncthreads();
    float2 (*src)[256] = s0;
    float2 (*dst)[256] = s1;
#pragma unroll
    for (int p = 0; p < 8; p++) {
        int Ns = 1 << p;
        for (int u = tid; u < 1024; u += 256) {
            int ch = u >> 7, j = u & 127;
            int jm = j & (Ns - 1);
            float2 a = src[ch][j];
            float2 b = src[ch][j + 128];
            float2 tw = stw[Ns - 1 + jm];
            float c = tw.x, s = fs * tw.y;
            float2 bw = make_float2(b.x * c - b.y * s, b.x * s + b.y * c);
            int idxD = ((j - jm) << 1) + jm;
            dst[ch][idxD]      = make_float2(a.x + bw.x, a.y + bw.y);
            dst[ch][idxD + Ns] = make_float2(a.x - bw.x, a.y - bw.y);
        }
        __syncthreads();
        float2 (*tmp)[256] = src; src = dst; dst = tmp;
    }
    for (int i = tid; i < 2048; i += 256) {
        int k2 = i >> 3, ch = i & 7;
        float2 w = g_btw[(n1 * k2) & 32767];
        float c = w.x, s = fs * w.y;
        float2 v = src[ch][k2];
        g_Z[((size_t)k2 * 128 + n1) * 64 + c0 + ch] =
            make_float2(v.x * c - v.y * s, v.x * s + v.y * c);
    }
}

// -------------------- batch-axis FFT, step 2 --------------------------------
__global__ __launch_bounds__(256)
void fft_b_step2(float fs, float scale)
{
    __shared__ float2 s0[8][128];
    __shared__ float2 s1[8][128];
    __shared__ float2 stw[127];
    int tid = threadIdx.x;
    int k2 = blockIdx.x;
    int c0 = blockIdx.y << 3;
    for (int i = tid; i < 127; i += 256) stw[i] = g_stw2[i];
    for (int i = tid; i < 1024; i += 256) {
        int n1 = i >> 3, ch = i & 7;
        s0[ch][n1] = g_Z[((size_t)k2 * 128 + n1) * 64 + c0 + ch];
    }
    __syncthreads();
    float2 (*src)[128] = s0;
    float2 (*dst)[128] = s1;
#pragma unroll
    for (int p = 0; p < 7; p++) {
        int Ns = 1 << p;
        for (int u = tid; u < 512; u += 256) {
            int ch = u >> 6, j = u & 63;
            int jm = j & (Ns - 1);
            float2 a = src[ch][j];
            float2 b = src[ch][j + 64];
            float2 tw = stw[Ns - 1 + jm];
            float c = tw.x, s = fs * tw.y;
            float2 bw = make_float2(b.x * c - b.y * s, b.x * s + b.y * c);
            int idxD = ((j - jm) << 1) + jm;
            dst[ch][idxD]      = make_float2(a.x + bw.x, a.y + bw.y);
            dst[ch][idxD + Ns] = make_float2(a.x - bw.x, a.y - bw.y);
        }
        __syncthreads();
        float2 (*tmp)[128] = src; src = dst; dst = tmp;
    }
    for (int i = tid; i < 1024; i += 256) {
        int k1 = i >> 3, ch = i & 7;
        float2 v = src[ch][k1];
        g_bufB[(size_t)(k2 + (k1 << 8)) * 64 + c0 + ch] =
            make_float2(v.x * scale, v.y * scale);
    }
}

// -------------------- FNO core (16 rows/block, padded weights) --------------
__global__ __launch_bounds__(1024)
void mid_kernel(const float* __restrict__ lin1W, const float* __restrict__ lin1b,
                const float* __restrict__ lin2W, const float* __restrict__ lin2b)
{
    __shared__ float L1t[64 * 65];
    __shared__ float L2t[64 * 65];
    __shared__ float yre[16][64], yim[16][64];
    __shared__ float2 sP[64], sM[64];
    int tid = threadIdx.x;
    int row0 = blockIdx.x << 4;
    for (int i = tid; i < 4096; i += 1024) {
        int o = i >> 6, w = i & 63;
        L1t[o * 65 + w] = lin1W[i];
        L2t[o * 65 + w] = lin2W[i];
    }
    if (tid < 64) { sP[tid] = g_P[tid]; sM[tid] = g_M[tid]; }
    int r = tid >> 6, w = tid & 63;
    float2 xh = g_bufB[(size_t)(row0 + r) * 64 + w];
    __syncthreads();
    {
        float rp = fmaxf(xh.x, 0.f), rn = fmaxf(-xh.x, 0.f);
        float ip = fmaxf(xh.y, 0.f), im2 = fmaxf(-xh.y, 0.f);
        float2 P = sP[w], Mv = sM[w];
        yre[r][w] = rp * P.x - ip * P.y + rn * Mv.x - im2 * Mv.y;
        yim[r][w] = rp * P.y + ip * P.x + rn * Mv.y + im2 * Mv.x;
    }
    __syncthreads();
    int o = w;
    float re = lin1b[o], im = 0.f;
#pragma unroll 16
    for (int ww = 0; ww < 64; ww++) {
        float lw = L1t[o * 65 + ww];
        re = fmaf(lw, yre[r][ww], re);
        im = fmaf(lw, yim[r][ww], im);
    }
    re = fmaxf(re, 0.f);
    im = fmaxf(im, 0.f);
    __syncthreads();
    yre[r][o] = re;
    yim[r][o] = im;
    __syncthreads();
    re = lin2b[o]; im = 0.f;
#pragma unroll 16
    for (int ww = 0; ww < 64; ww++) {
        float lw = L2t[o * 65 + ww];
        re = fmaf(lw, yre[r][ww], re);
        im = fmaf(lw, yim[r][ww], im);
    }
    g_bufA[(size_t)(row0 + r) * 64 + o] = make_float2(re, im);
}

// -------------------- inverse row DFT-64 + W_out (16 rows/block) ------------
__global__ __launch_bounds__(1024)
void out_kernel(const float* __restrict__ Wout, const float* __restrict__ bout,
                float* __restrict__ outp, int interleaved)
{
    __shared__ float Wt[128 * 65];
    __shared__ float2 szu[16][64];
    int tid = threadIdx.x;
    int row0 = blockIdx.x << 4;
    for (int i = tid; i < 8192; i += 1024) {
        int f = i >> 6, w = i & 63;
        Wt[f * 65 + w] = Wout[i];
    }
    {
        int r = tid >> 6, k = tid & 63;
        szu[r][k] = g_bufB[(size_t)(row0 + r) * 64 + k];
    }
    __syncthreads();
    float ure, uim;
    {
        int r = tid >> 6, w = tid & 63;
        float re = 0.f, im = 0.f;
#pragma unroll 16
        for (int k = 0; k < 64; k++) {
            float2 t = g_dftI[(k << 6) + w];
            float2 z = szu[r][k];
            re += z.x * t.x - z.y * t.y;
            im += z.x * t.y + z.y * t.x;
        }
        ure = re; uim = im;
    }
    __syncthreads();
    {
        int r = tid >> 6, w = tid & 63;
        szu[r][w] = make_float2(ure, uim);
    }
    __syncthreads();
#pragma unroll
    for (int it = 0; it < 2; it++) {
        int idx = it * 1024 + tid;
        int r = idx >> 7, f = idx & 127;
        float re = bout[f], im = 0.f;
#pragma unroll 16
        for (int w = 0; w < 64; w++) {
            float lw = Wt[f * 65 + w];
            float2 u = szu[r][w];
            re = fmaf(lw, u.x, re);
            im = fmaf(lw, u.y, im);
        }
        size_t oidx = (size_t)(row0 + r) * 128 + f;
        if (interleaved) {
            reinterpret_cast<float2*>(outp)[oidx] = make_float2(re, im);
        } else {
            outp[oidx] = re;
        }
    }
}

// ---------------------------------------------------------------------------
extern "C" void kernel_launch(void* const* d_in, const int* in_sizes, int n_in,
                              void* d_out, int out_size)
{
    (void)in_sizes; (void)n_in;
    const float* geom  = (const float*)d_in[0];
    const float* W_in  = (const float*)d_in[1];
    const float* b_in  = (const float*)d_in[2];
    const float* W_h1  = (const float*)d_in[3];
    const float* b_h1  = (const float*)d_in[4];
    const float* W_h2  = (const float*)d_in[5];
    const float* b_h2  = (const float*)d_in[6];
    const float* w0    = (const float*)d_in[7];
    const float* w1    = (const float*)d_in[8];
    const float* lin1W = (const float*)d_in[9];
    const float* lin1b = (const float*)d_in[10];
    const float* lin2W = (const float*)d_in[11];
    const float* lin2b = (const float*)d_in[12];
    const float* Wout  = (const float*)d_in[13];
    const float* bout  = (const float*)d_in[14];

    const int GSM128 = 6 * 8192 + 6 * 128 * 64;   // 98304 bytes (BN=128)
    const int GSM64  = 6 * 8192 + 6 * 64 * 64;    // 73728 bytes (BN=64)
    cudaFuncSetAttribute(mma_gemm<128, 0>, cudaFuncAttributeMaxDynamicSharedMemorySize, GSM128);
    cudaFuncSetAttribute(mma_gemm<128, 1>, cudaFuncAttributeMaxDynamicSharedMemorySize, GSM128);
    cudaFuncSetAttribute(mma_gemm<64, 2>,  cudaFuncAttributeMaxDynamicSharedMemorySize, GSM64);

    init_tables<<<64, 256>>>(w0, w1);

    // splits + GEMMs (mma_gemm<128,0> stays in the ncu capture slot)
    split_kernel<0><<<(NB * 512 / 4) / 256, 256>>>(geom, NB * 512 / 4);
    split_kernel<1><<<(1024 * 512 / 4) / 256, 256>>>(W_in, 1024 * 512 / 4);
    mma_gemm<128, 0><<<dim3(1024 / 128, NB / 128), 256, GSM128>>>(b_in, NB, 1024, 512);
    split_kernel<2><<<(512 * 1024 / 4) / 256, 256>>>(W_h1, 512 * 1024 / 4);
    mma_gemm<128, 1><<<dim3(512 / 128, NB / 128), 256, GSM128>>>(b_h1, NB, 512, 1024);
    split_kernel<3><<<(64 * 512 / 4) / 256, 256>>>(W_h2, 64 * 512 / 4);
    mma_gemm<64, 2><<<dim3(1, NB / 128), 256, GSM64>>>(b_h2, NB, 64, 512);

    // forward fftn
    fwd_row_dft<<<NB / 16, 1024>>>();
    fft_b_step1<<<dim3(128, 8), 256>>>(1.f);
    fft_b_step2<<<dim3(256, 8), 256>>>(1.f, 1.0f);

    // FNO core
    mid_kernel<<<NB / 16, 1024>>>(lin1W, lin1b, lin2W, lin2b);

    // inverse batch-axis FFT (conjugated twiddles)
    fft_b_step1<<<dim3(128, 8), 256>>>(-1.f);
    fft_b_step2<<<dim3(256, 8), 256>>>(-1.f, 1.0f / 32768.0f);

    // inverse row DFT-64 + output projection
    int interleaved = (out_size >= 2 * NB * 128) ? 1 : 0;
    out_kernel<<<NB / 16, 1024>>>(Wout, bout, (float*)d_out, interleaved);
}